// round 13
// baseline (speedup 1.0000x reference)
#include <cuda_runtime.h>
#include <cuda_bf16.h>
#include <math.h>
#include <stdint.h>

#define B  8
#define H  512
#define W  512
#define PLANE (H*W)
#define NPIX (B*PLANE)

// ---------------------------------------------------------------------------
// Scratch
// ---------------------------------------------------------------------------
__device__ __align__(16) uint2 g_f1p[(size_t)B*16*PLANE]; // packed split pairs (c, c+8)
__device__ __align__(16) uint2 g_f2p[(size_t)B* 8*PLANE];
__device__ float g_f [(size_t)B*8*PLANE];
__device__ float g_maps[(size_t)3*NPIX];
__device__ float g_fused[(size_t)NPIX];
__device__ unsigned g_h1[8192];
__device__ unsigned g_h2[4*8192];
__device__ unsigned g_h3[4*64];
__device__ float2 g_stats[32];
__device__ float g_thr[64];

__device__ uint32_t g_w1b[9*4*32], g_w1s[9*4*32];          // [s][k4][co32]
__device__ __align__(16) uint32_t g_w2b[2*9*4*8*4], g_w2s[2*9*4*8*4];
__device__ __align__(16) uint32_t g_w3b[9*4*8*4],   g_w3s[9*4*8*4];

struct QState {
    unsigned pref1[4];
    unsigned rem[4];
    unsigned pref2[4];
    float q25, q75, iqr;
};
__device__ QState g_qs;

// ---------------------------------------------------------------------------
__global__ void zero_k() {
    int i = blockIdx.x * blockDim.x + threadIdx.x;
    int n = gridDim.x * blockDim.x;
    for (int j = i; j < 8192; j += n)    g_h1[j] = 0u;
    for (int j = i; j < 4*8192; j += n)  g_h2[j] = 0u;
    for (int j = i; j < 4*64; j += n)    g_h3[j] = 0u;
    for (int j = i; j < 32; j += n)      g_stats[j] = make_float2(0.f, 0.f);
}

__device__ __forceinline__ uint32_t f2tf(float f) {
    uint32_t r;
    asm("cvt.rna.tf32.f32 %0, %1;" : "=r"(r) : "f"(f));
    return r;
}
__device__ __forceinline__ void tf_split(float v, uint32_t& vb, uint32_t& vs) {
    vb = f2tf(v);
    vs = f2tf(v - __uint_as_float(vb));
}
__device__ __forceinline__ uint32_t bpack2(float v0, float v1, uint32_t& smw) {
    __nv_bfloat16 b0 = __float2bfloat16(v0), b1 = __float2bfloat16(v1);
    float r0 = v0 - __bfloat162float(b0);
    float r1 = v1 - __bfloat162float(b1);
    __nv_bfloat16 s0 = __float2bfloat16(r0), s1 = __float2bfloat16(r1);
    smw = (uint32_t)__bfloat16_as_ushort(s0) | ((uint32_t)__bfloat16_as_ushort(s1) << 16);
    return (uint32_t)__bfloat16_as_ushort(b0) | ((uint32_t)__bfloat16_as_ushort(b1) << 16);
}
__device__ __forceinline__ void mma16(float* d, const uint32_t* a, uint32_t b0, uint32_t b1) {
    asm("mma.sync.aligned.m16n8k16.row.col.f32.bf16.bf16.f32 "
        "{%0,%1,%2,%3}, {%4,%5,%6,%7}, {%8,%9}, {%0,%1,%2,%3};"
        : "+f"(d[0]), "+f"(d[1]), "+f"(d[2]), "+f"(d[3])
        : "r"(a[0]), "r"(a[1]), "r"(a[2]), "r"(a[3]), "r"(b0), "r"(b1));
}
__device__ __forceinline__ void mma4(float* d, uint32_t a0, uint32_t a1, uint32_t b0) {
    asm("mma.sync.aligned.m16n8k4.row.col.f32.tf32.tf32.f32 "
        "{%0,%1,%2,%3}, {%4,%5}, {%6}, {%0,%1,%2,%3};"
        : "+f"(d[0]), "+f"(d[1]), "+f"(d[2]), "+f"(d[3])
        : "r"(a0), "r"(a1), "r"(b0));
}
__device__ __forceinline__ float lrelu(float v) { return v >= 0.f ? v : 0.2f * v; }

// ---------------------------------------------------------------------------
// Weight prep (layouts unchanged from r11)
// ---------------------------------------------------------------------------
__global__ void prep_k(const float* __restrict__ w1, const float* __restrict__ w2,
                       const float* __restrict__ w3) {
    int i0 = blockIdx.x * blockDim.x + threadIdx.x;
    int n = gridDim.x * blockDim.x;
    for (int j = i0; j < 9*4*32; j += n) {
        int s = j / 128, k = (j >> 5) & 3, co = j & 31;
        tf_split(w1[co*36 + k*9 + s], g_w1b[j], g_w1s[j]);
    }
    for (int j = i0; j < 2*9*4*8*4; j += n) {
        int reg = j & 3, nq = (j >> 2) & 7, tt = (j >> 5) & 3;
        int s = (j >> 7) % 9, chunk = j / 1152;
        int co = nq + 8*(reg & 1);
        int pu = tt + 4*(reg >> 1);
        float v0 = w2[co*288 + (chunk*16 + pu)*9 + s];
        float v1 = w2[co*288 + (chunk*16 + pu + 8)*9 + s];
        uint32_t smw;
        uint32_t bg = bpack2(v0, v1, smw);
        g_w2b[j] = bg; g_w2s[j] = smw;
    }
    for (int j = i0; j < 9*4*8*4; j += n) {
        int reg = j & 3, nq = (j >> 2) & 7, tt = (j >> 5) & 3;
        int s = (j >> 7) % 9;
        int co = nq + 8*(reg & 1);
        int pu = tt + 4*(reg >> 1);
        float v0 = 0.f, v1 = 0.f;
        if (co < 8) {
            v0 = w3[co*144 + pu*9 + s];
            v1 = w3[co*144 + (pu + 8)*9 + s];
        }
        uint32_t smw;
        uint32_t bg = bpack2(v0, v1, smw);
        g_w3b[j] = bg; g_w3s[j] = smw;
    }
}

// ---------------------------------------------------------------------------
// conv1: 4 -> 32, leaky. Block 8 rows x 32 cols, 1 row/warp, 3 CTAs/SM.
// ---------------------------------------------------------------------------
__global__ __launch_bounds__(256, 3)
void conv1_k(const float* __restrict__ in, const float* __restrict__ bias) {
    __shared__ uint2 t1[4*344];          // 4ch x (10*34), ch stride 344
    const int tid = threadIdx.x;
    const int wid = tid >> 5, lane = tid & 31;
    const int nq = lane >> 2, tt = lane & 3;
    const int x0 = blockIdx.x * 32, y0 = blockIdx.y * 8, b = blockIdx.z;

    for (int i = tid; i < 4*340; i += 256) {
        int c = i / 340, rem = i % 340;
        int yy = rem / 34, xx = rem % 34;
        int gy = y0 + yy - 1, gx = x0 + xx - 1;
        float v = 0.f;
        if (gy >= 0 && gy < H && gx >= 0 && gx < W)
            v = in[(((size_t)b*4 + c)*H + gy)*W + gx];
        uint32_t vb, vs;
        tf_split(v, vb, vs);
        t1[c*344 + yy*34 + xx] = make_uint2(vb, vs);
    }
    __syncthreads();

    float acc[2][4][4];
#pragma unroll
    for (int m = 0; m < 2; m++)
#pragma unroll
        for (int g = 0; g < 4; g++)
#pragma unroll
            for (int q = 0; q < 4; q++) acc[m][g][q] = 0.f;

#pragma unroll
    for (int s = 0; s < 9; s++) {
        const int kh = s / 3, kw = s % 3;
        int wb = (s*4 + tt)*32;
        uint32_t a0b = g_w1b[wb + nq],      a1b = g_w1b[wb + nq + 8];
        uint32_t a2b = g_w1b[wb + 16 + nq], a3b = g_w1b[wb + 24 + nq];
        uint32_t a0s = g_w1s[wb + nq],      a1s = g_w1s[wb + nq + 8];
        uint32_t a2s = g_w1s[wb + 16 + nq], a3s = g_w1s[wb + 24 + nq];
        int base = tt*344 + (wid + kh)*34 + nq + kw;
#pragma unroll
        for (int g = 0; g < 4; g++) {
            uint2 bv = t1[base + g*8];
            mma4(acc[0][g], a0b, a1b, bv.x);
            mma4(acc[0][g], a0s, a1s, bv.x);
            mma4(acc[0][g], a0b, a1b, bv.y);
            mma4(acc[1][g], a2b, a3b, bv.x);
            mma4(acc[1][g], a2s, a3s, bv.x);
            mma4(acc[1][g], a2b, a3b, bv.y);
        }
    }

    const int gy = y0 + wid;
#pragma unroll
    for (int m = 0; m < 2; m++) {
        int co0 = m*16 + nq;
        float b0 = bias[co0], b8 = bias[co0 + 8];
        size_t plane = (size_t)(b*16 + m*8 + nq);
#pragma unroll
        for (int g = 0; g < 4; g++) {
            int pe = x0 + g*8 + 2*tt;
            float v0 = lrelu(acc[m][g][0] + b0);
            float v1 = lrelu(acc[m][g][1] + b0);
            float v2 = lrelu(acc[m][g][2] + b8);
            float v3 = lrelu(acc[m][g][3] + b8);
            uint32_t se, so;
            uint32_t be = bpack2(v0, v2, se);
            uint32_t bo = bpack2(v1, v3, so);
            *(uint4*)&g_f1p[plane*PLANE + (size_t)gy*W + pe] = make_uint4(be, se, bo, so);
        }
    }
}

// ---------------------------------------------------------------------------
// conv2/conv3: bf16 m16n8k16, 1 row/warp, 3 CTAs/SM.
// Tile uint2 slots, rotation rr(pix) as in r11; one LDS.128 per MMA-triple.
// ---------------------------------------------------------------------------
template<int CHUNKS, int COUT, bool LEAKY, bool PACKOUT>
__global__ __launch_bounds__(256, 3)
void convP_k(const uint2* __restrict__ inp, const uint4* __restrict__ wb4,
             const uint4* __restrict__ ws4, const float* __restrict__ bias,
             uint2* __restrict__ outp, float* __restrict__ outf) {
    extern __shared__ uint2 tile[];   // [660*8]
    const int tid = threadIdx.x;
    const int wid = tid >> 5, lane = tid & 31;
    const int nq = lane >> 2, tt = lane & 3;
    const int x0 = blockIdx.x * 64, y0 = blockIdx.y * 8, b = blockIdx.z;

    float acc[8][4];
#pragma unroll
    for (int g = 0; g < 8; g++)
#pragma unroll
        for (int q = 0; q < 4; q++) acc[g][q] = 0.f;

#pragma unroll 1
    for (int chunk = 0; chunk < CHUNKS; chunk++) {
        __syncthreads();
#pragma unroll
        for (int u = 0; u < 8; u++) {
            for (int pix = tid; pix < 660; pix += 256) {
                int yy = pix / 66, xx = pix - yy*66;
                int gy = y0 + yy - 1, gx = x0 + xx - 1;
                uint2 v = make_uint2(0u, 0u);
                if (gy >= 0 && gy < H && gx >= 0 && gx < W)
                    v = inp[(((size_t)b*CHUNKS + chunk)*8 + u)*PLANE + (size_t)gy*W + gx];
                int rr = (pix + (pix >> 2)) & 3;
                int pos = 2*(((u & 3) + rr) & 3) + (u >> 2);
                tile[pix*8 + pos] = v;
            }
        }
        __syncthreads();

#pragma unroll
        for (int s = 0; s < 9; s++) {
            const int kh = s / 3, kw = s % 3;
            uint4 A = wb4[((chunk*9 + s)*4 + tt)*8 + nq];
            uint4 S = ws4[((chunk*9 + s)*4 + tt)*8 + nq];
            uint32_t ab[4]  = {A.x, A.y, A.z, A.w};
            uint32_t as_[4] = {S.x, S.y, S.z, S.w};
#pragma unroll
            for (int g = 0; g < 8; g++) {
                int pix = (wid + kh)*66 + g*8 + nq + kw;
                int rr = (pix + (pix >> 2)) & 3;
                int t = pix*8 + 2*((tt + rr) & 3);
                uint4 Bv = *(const uint4*)&tile[t];
                mma16(acc[g], ab,  Bv.x, Bv.z);
                mma16(acc[g], as_, Bv.x, Bv.z);
                mma16(acc[g], ab,  Bv.y, Bv.w);
            }
        }
    }

    const int gy = y0 + wid;
    if (PACKOUT) {
        float b0 = bias[nq], b8 = bias[nq + 8];
        size_t plane = (size_t)(b*8 + nq);
#pragma unroll
        for (int g = 0; g < 8; g++) {
            int pe = x0 + g*8 + 2*tt;
            float v0 = acc[g][0] + b0, v1 = acc[g][1] + b0;
            float v2 = acc[g][2] + b8, v3 = acc[g][3] + b8;
            if (LEAKY) { v0 = lrelu(v0); v1 = lrelu(v1); v2 = lrelu(v2); v3 = lrelu(v3); }
            uint32_t se, so;
            uint32_t be = bpack2(v0, v2, se);
            uint32_t bo = bpack2(v1, v3, so);
            *(uint4*)&outp[plane*PLANE + (size_t)gy*W + pe] = make_uint4(be, se, bo, so);
        }
    } else {
        float b0 = bias[nq];
#pragma unroll
        for (int g = 0; g < 8; g++) {
            int pe = x0 + g*8 + 2*tt;
            float2 o0;
            o0.x = acc[g][0] + b0; o0.y = acc[g][1] + b0;
            if (LEAKY) { o0.x = lrelu(o0.x); o0.y = lrelu(o0.y); }
            *(float2*)&outf[(((size_t)b*COUT + nq)*H + gy)*W + pe] = o0;
        }
    }
}

// ---------------------------------------------------------------------------
// Multi-scale box std maps (unchanged)
// ---------------------------------------------------------------------------
__device__ __forceinline__ int refl(int i) {
    return i < 0 ? -i : (i > H - 1 ? 2*(H - 1) - i : i);
}

__global__ __launch_bounds__(512)
void boxstd_k() {
    constexpr int ROWS = 64;
    extern __shared__ float bsm[];
    float* csA  = bsm;
    float* csB  = bsm + 4096;
    float* pref = bsm + 8192;

    const int j    = threadIdx.x;
    const int lane = j & 31;
    const int wid  = j >> 5;
    const int strip = blockIdx.x;
    const int scale = blockIdx.y;
    const int b     = blockIdx.z;

    const int K = (scale == 0) ? 11 : (scale == 1) ? 25 : 49;
    const int P = K >> 1;
    const float inv = 1.f / (float)(K * K);
    const int r0 = strip * ROWS;

    for (int c = 0; c < 8; c++) {
        const float* fp = g_f + ((size_t)(b*8 + c)) * PLANE;
        float s = 0.f, s2 = 0.f;
        for (int i = r0 - P; i <= r0 + P; i++) {
            float v = fp[refl(i)*W + j];
            s += v;
            s2 = fmaf(v, v, s2);
        }
        csA[c*512 + j] = s;
        csB[c*512 + j] = s2;
    }

    const int sc = wid & 7, sq = wid >> 3;
    float* src = (sq ? csB : csA) + sc*512;
    float* pr  = pref + wid*513;

    for (int r = r0; r < r0 + ROWS; r++) {
        if (r > r0) {
            int ra = refl(r + P), rs = refl(r - 1 - P);
#pragma unroll
            for (int c = 0; c < 8; c++) {
                const float* fp = g_f + ((size_t)(b*8 + c)) * PLANE;
                float va = fp[ra*W + j], vs = fp[rs*W + j];
                csA[c*512 + j] += va - vs;
                csB[c*512 + j] += va*va - vs*vs;
            }
        }
        __syncthreads();

        {
            float seg[16];
            float run = 0.f;
            int base = lane * 16;
#pragma unroll
            for (int i = 0; i < 16; i++) { run += src[base + i]; seg[i] = run; }
            float v = run;
#pragma unroll
            for (int d = 1; d < 32; d <<= 1) {
                float t = __shfl_up_sync(0xffffffffu, v, d);
                if (lane >= d) v += t;
            }
            float carry = v - run;
#pragma unroll
            for (int i = 0; i < 16; i++) pr[base + 1 + i] = seg[i] + carry;
            if (lane == 0) pr[0] = 0.f;
        }
        __syncthreads();

        const int lo = j - P, hi = j + P;
        const int loC = max(lo, 0), hiC = min(hi, W - 1);
        float rowacc = 0.f;
#pragma unroll
        for (int c = 0; c < 8; c++) {
            const float* pA = pref + c*513;
            const float* pB = pref + (8 + c)*513;
            float Sx = pA[hiC + 1] - pA[loC];
            float Sy = pB[hiC + 1] - pB[loC];
            if (lo < 0) {
                Sx += pA[-lo + 1] - pA[1];
                Sy += pB[-lo + 1] - pB[1];
            }
            if (hi > W - 1) {
                Sx += pA[W - 1] - pA[2*(W - 1) - hi];
                Sy += pB[W - 1] - pB[2*(W - 1) - hi];
            }
            float m  = Sx * inv;
            float m2 = Sy * inv;
            rowacc += sqrtf(fmaxf(m2 - m*m, 1e-6f));
        }
        g_maps[(size_t)scale*NPIX + ((size_t)b*H + r)*W + j] =
            powf(rowacc * 0.125f, 0.8f);
    }
}

// ---------------------------------------------------------------------------
// Fusion + level-1 histogram
// ---------------------------------------------------------------------------
__global__ void fuse_hist1_k(const float* __restrict__ fw, const float* __restrict__ fb) {
    __shared__ unsigned h[8192];
    for (int i = threadIdx.x; i < 8192; i += blockDim.x) h[i] = 0u;
    __syncthreads();
    const float w0 = fw[0], w1 = fw[1], w2 = fw[2], b0 = fb[0];
    const size_t N = NPIX;
    for (size_t i = (size_t)blockIdx.x*blockDim.x + threadIdx.x; i < N;
         i += (size_t)gridDim.x*blockDim.x) {
        float v = w0*g_maps[i] + w1*g_maps[i + N] + w2*g_maps[i + 2*N] + b0;
        v = fmaxf(v, 0.f);
        g_fused[i] = v;
        atomicAdd(&h[__float_as_uint(v) >> 19], 1u);
    }
    __syncthreads();
    for (int i = threadIdx.x; i < 8192; i += blockDim.x)
        if (h[i]) atomicAdd(&g_h1[i], h[i]);
}

__device__ void findRank(const unsigned* __restrict__ hist, int nbins, unsigned rank,
                         unsigned* sbin, unsigned* srem,
                         unsigned* sp, unsigned* sb) {
    __syncthreads();
    const int tid = threadIdx.x;
    const int chunk = nbins / 256;
    unsigned loc = 0;
    for (int i = 0; i < chunk; i++) loc += hist[tid*chunk + i];
    sp[tid] = loc;
    __syncthreads();
    if (tid == 0) {
        unsigned c = 0;
        for (int i = 0; i < 256; i++) { sb[i] = c; c += sp[i]; }
    }
    __syncthreads();
    unsigned cum = sb[tid];
    for (int i = 0; i < chunk; i++) {
        unsigned cnt = hist[tid*chunk + i];
        if (rank >= cum && rank < cum + cnt) { *sbin = tid*chunk + i; *srem = rank - cum; }
        cum += cnt;
    }
    __syncthreads();
}

__global__ void scan1_k() {
    __shared__ unsigned sp[256], sb[256];
    __shared__ unsigned rbin, rrem;
    const unsigned ranks[4] = {524287u, 524288u, 1572863u, 1572864u};
    for (int r = 0; r < 4; r++) {
        findRank(g_h1, 8192, ranks[r], &rbin, &rrem, sp, sb);
        if (threadIdx.x == 0) { g_qs.pref1[r] = rbin; g_qs.rem[r] = rrem; }
        __syncthreads();
    }
}

// Single-pass level-2: all 4 rank histograms in 128KB smem
__global__ void hist2_k() {
    extern __shared__ unsigned h2s[];   // 4*8192
    for (int i = threadIdx.x; i < 4*8192; i += blockDim.x) h2s[i] = 0u;
    __syncthreads();
    unsigned p0 = g_qs.pref1[0], p1 = g_qs.pref1[1];
    unsigned p2 = g_qs.pref1[2], p3 = g_qs.pref1[3];
    const uint4* fp = (const uint4*)g_fused;
    const size_t N4 = NPIX/4;
    for (size_t i = (size_t)blockIdx.x*blockDim.x + threadIdx.x; i < N4;
         i += (size_t)gridDim.x*blockDim.x) {
        uint4 v = fp[i];
        uint32_t bb[4] = {v.x, v.y, v.z, v.w};
#pragma unroll
        for (int e = 0; e < 4; e++) {
            unsigned hi = bb[e] >> 19, mid = (bb[e] >> 6) & 8191u;
            if (hi == p0) atomicAdd(&h2s[mid], 1u);
            if (hi == p1) atomicAdd(&h2s[8192 + mid], 1u);
            if (hi == p2) atomicAdd(&h2s[16384 + mid], 1u);
            if (hi == p3) atomicAdd(&h2s[24576 + mid], 1u);
        }
    }
    __syncthreads();
    for (int i = threadIdx.x; i < 4*8192; i += blockDim.x)
        if (h2s[i]) atomicAdd(&g_h2[i], h2s[i]);
}

__global__ void scan2_k() {
    __shared__ unsigned sp[256], sb[256];
    __shared__ unsigned rbin, rrem;
    for (int r = 0; r < 4; r++) {
        unsigned rank = g_qs.rem[r];
        findRank(g_h2 + r*8192, 8192, rank, &rbin, &rrem, sp, sb);
        if (threadIdx.x == 0) {
            g_qs.pref2[r] = (g_qs.pref1[r] << 13) | rbin;
            g_qs.rem[r]   = rrem;
        }
        __syncthreads();
    }
}

// Single-pass level-3
__global__ void hist3_k() {
    __shared__ unsigned h[4*64];
    for (int i = threadIdx.x; i < 4*64; i += blockDim.x) h[i] = 0u;
    __syncthreads();
    unsigned p0 = g_qs.pref2[0], p1 = g_qs.pref2[1];
    unsigned p2 = g_qs.pref2[2], p3 = g_qs.pref2[3];
    const uint4* fp = (const uint4*)g_fused;
    const size_t N4 = NPIX/4;
    for (size_t i = (size_t)blockIdx.x*blockDim.x + threadIdx.x; i < N4;
         i += (size_t)gridDim.x*blockDim.x) {
        uint4 v = fp[i];
        uint32_t bb[4] = {v.x, v.y, v.z, v.w};
#pragma unroll
        for (int e = 0; e < 4; e++) {
            unsigned hi = bb[e] >> 6, lo = bb[e] & 63u;
            if (hi == p0) atomicAdd(&h[lo], 1u);
            if (hi == p1) atomicAdd(&h[64 + lo], 1u);
            if (hi == p2) atomicAdd(&h[128 + lo], 1u);
            if (hi == p3) atomicAdd(&h[192 + lo], 1u);
        }
    }
    __syncthreads();
    for (int i = threadIdx.x; i < 4*64; i += blockDim.x)
        if (h[i]) atomicAdd(&g_h3[i], h[i]);
}

__global__ void scan3_k() {
    __shared__ float sv[4];
    const int r = threadIdx.x;
    if (r < 4) {
        unsigned rank = g_qs.rem[r];
        unsigned cum = 0, bin = 0;
        for (int i = 0; i < 64; i++) {
            unsigned c = g_h3[r*64 + i];
            if (rank >= cum && rank < cum + c) bin = (unsigned)i;
            cum += c;
        }
        sv[r] = __uint_as_float((g_qs.pref2[r] << 6) | bin);
    }
    __syncthreads();
    if (r == 0) {
        float q25 = sv[0] + 0.75f*(sv[1] - sv[0]);
        float q75 = sv[2] + 0.25f*(sv[3] - sv[2]);
        float iqr = q75 - q25;
        if (iqr < 1e-5f) iqr = 0.05f;
        g_qs.q25 = q25; g_qs.q75 = q75; g_qs.iqr = iqr;
    }
}

__global__ void xstats_k(const float* __restrict__ x) {
    const int bc = blockIdx.x;
    const int sl = blockIdx.y;
    const float* p = x + ((size_t)bc << 18) + (size_t)sl * 32768;
    float s = 0.f, s2 = 0.f;
    for (int i = threadIdx.x; i < 32768; i += 256) {
        float v = p[i];
        s += v;
        s2 = fmaf(v, v, s2);
    }
#pragma unroll
    for (int o = 16; o; o >>= 1) {
        s  += __shfl_xor_sync(0xffffffffu, s, o);
        s2 += __shfl_xor_sync(0xffffffffu, s2, o);
    }
    __shared__ float ss[8], ss2[8];
    int w = threadIdx.x >> 5, l = threadIdx.x & 31;
    if (l == 0) { ss[w] = s; ss2[w] = s2; }
    __syncthreads();
    if (threadIdx.x == 0) {
        float a = 0.f, a2 = 0.f;
        for (int i = 0; i < 8; i++) { a += ss[i]; a2 += ss2[i]; }
        atomicAdd(&g_stats[bc].x, a);
        atomicAdd(&g_stats[bc].y, a2);
    }
}

__global__ void thr_k(const float* __restrict__ chw) {
    const int t = threadIdx.x;
    const int c = t & 3;
    float w0 = chw[0], w1 = chw[1], w2 = chw[2], w3 = chw[3];
    float mx = fmaxf(fmaxf(w0, w1), fmaxf(w2, w3));
    float e0 = expf(w0 - mx), e1 = expf(w1 - mx), e2 = expf(w2 - mx), e3 = expf(w3 - mx);
    float se = e0 + e1 + e2 + e3;
    float cw = ((c == 0) ? e0 : (c == 1) ? e1 : (c == 2) ? e2 : e3) / se;

    float2 st = g_stats[t];
    const float N = (float)PLANE;
    float var = (st.y - st.x*st.x/N) / (N - 1.f);
    float gstd = sqrtf(fmaxf(var, 0.f));

    float q25 = g_qs.q25, q75 = g_qs.q75, iqr = g_qs.iqr;
    float lower = q25 - 0.5f*iqr;
    float upper = q75 + 0.5f*iqr;
    float gf = fminf(fmaxf(gstd*5.f, 0.5f), 2.f);
    lower *= gf; upper *= gf;
    float cf = fminf(fmaxf(cw*gstd*2.f, 0.8f), 1.2f);
    lower *= cf; upper *= cf;

    float d = fabsf(upper - lower);
#pragma unroll
    for (int o = 16; o; o >>= 1) d = fminf(d, __shfl_xor_sync(0xffffffffu, d, o));
    if (d < 1e-5f) {
        float mt = 0.5f*(upper + lower);
        lower = mt - 0.05f;
        upper = mt + 0.05f;
    }
    g_thr[t]      = lower;
    g_thr[32 + t] = fmaxf(upper - lower, 1e-5f);
}

__global__ void mask_k(float* __restrict__ out) {
    for (size_t i = (size_t)blockIdx.x*blockDim.x + threadIdx.x; i < (size_t)NPIX;
         i += (size_t)gridDim.x*blockDim.x) {
        int b = (int)(i >> 18);
        float v = g_fused[i];
        float acc = 0.f;
#pragma unroll
        for (int c = 0; c < 4; c++) {
            float lo  = g_thr[b*4 + c];
            float dif = g_thr[32 + b*4 + c];
            float nrm = fminf(fmaxf((v - lo)/dif, 0.f), 1.f);
            acc += 1.f/(1.f + expf(3.f - 6.f*nrm));
        }
        out[i] = 0.25f*acc;
    }
}

// ---------------------------------------------------------------------------
// Launch
// ---------------------------------------------------------------------------
extern "C" void kernel_launch(void* const* d_in, const int* in_sizes, int n_in,
                              void* d_out, int out_size) {
    const float* x        = (const float*)d_in[0];
    const float* conv1_w  = (const float*)d_in[1];
    const float* conv1_b  = (const float*)d_in[2];
    const float* conv2_w  = (const float*)d_in[3];
    const float* conv2_b  = (const float*)d_in[4];
    const float* conv3_w  = (const float*)d_in[5];
    const float* conv3_b  = (const float*)d_in[6];
    const float* fusion_w = (const float*)d_in[7];
    const float* fusion_b = (const float*)d_in[8];
    const float* chw      = (const float*)d_in[9];
    float* out = (float*)d_out;

    uint2* f1p; cudaGetSymbolAddress((void**)&f1p, g_f1p);
    uint2* f2p; cudaGetSymbolAddress((void**)&f2p, g_f2p);
    float* f  ; cudaGetSymbolAddress((void**)&f  , g_f);
    uint4 *w2b, *w2s, *w3b, *w3s;
    cudaGetSymbolAddress((void**)&w2b, g_w2b);
    cudaGetSymbolAddress((void**)&w2s, g_w2s);
    cudaGetSymbolAddress((void**)&w3b, g_w3b);
    cudaGetSymbolAddress((void**)&w3s, g_w3s);

    const int smemP  = 660 * 8 * 8;                  // 42240
    const int smemBX = (4096 + 4096 + 16*513) * 4;   // 65668
    const int smemH2 = 4 * 8192 * 4;                 // 131072
    cudaFuncSetAttribute(convP_k<2, 16, true, true>,  cudaFuncAttributeMaxDynamicSharedMemorySize, smemP);
    cudaFuncSetAttribute(convP_k<1, 8, false, false>, cudaFuncAttributeMaxDynamicSharedMemorySize, smemP);
    cudaFuncSetAttribute(boxstd_k, cudaFuncAttributeMaxDynamicSharedMemorySize, smemBX);
    cudaFuncSetAttribute(hist2_k,  cudaFuncAttributeMaxDynamicSharedMemorySize, smemH2);

    zero_k<<<64, 256>>>();
    prep_k<<<16, 256>>>(conv1_w, conv2_w, conv3_w);

    conv1_k<<<dim3(W/32, H/8, B), 256>>>(x, conv1_b);
    convP_k<2, 16, true, true><<<dim3(W/64, H/8, B), 256, smemP>>>(f1p, w2b, w2s, conv2_b, f2p, 0);
    convP_k<1, 8, false, false><<<dim3(W/64, H/8, B), 256, smemP>>>(f2p, w3b, w3s, conv3_b, 0, f);

    boxstd_k<<<dim3(H/64, 3, B), 512, smemBX>>>();

    fuse_hist1_k<<<448, 256>>>(fusion_w, fusion_b);
    scan1_k<<<1, 256>>>();
    hist2_k<<<148, 512, smemH2>>>();
    scan2_k<<<1, 256>>>();
    hist3_k<<<256, 256>>>();
    scan3_k<<<1, 32>>>();

    xstats_k<<<dim3(32, 8), 256>>>(x);
    thr_k<<<1, 32>>>(chw);

    mask_k<<<1024, 256>>>(out);
}

// round 14
// speedup vs baseline: 1.0636x; 1.0636x over previous
#include <cuda_runtime.h>
#include <cuda_bf16.h>
#include <math.h>
#include <stdint.h>

#define B  8
#define H  512
#define W  512
#define PLANE (H*W)
#define NPIX (B*PLANE)

// ---------------------------------------------------------------------------
// Scratch
// ---------------------------------------------------------------------------
__device__ __align__(16) uint2 g_f1p[(size_t)B*16*PLANE]; // packed split pairs (c, c+8)
__device__ __align__(16) uint2 g_f2p[(size_t)B* 8*PLANE];
__device__ float g_f [(size_t)B*8*PLANE];
__device__ float g_maps[(size_t)3*NPIX];
__device__ float g_fused[(size_t)NPIX];
__device__ unsigned g_h1[8192];
__device__ unsigned g_h2[4*8192];
__device__ unsigned g_h3[4*64];
__device__ float2 g_stats[32];
__device__ float g_thr[64];

__device__ uint32_t g_w1b[9*4*32], g_w1s[9*4*32];          // [s][k4][co32]
__device__ __align__(16) uint32_t g_w2b[2*9*4*8*4], g_w2s[2*9*4*8*4];
__device__ __align__(16) uint32_t g_w3b[9*4*8*4],   g_w3s[9*4*8*4];

struct QState {
    unsigned pref1[4];
    unsigned rem[4];
    unsigned pref2[4];
    float q25, q75, iqr;
};
__device__ QState g_qs;

// ---------------------------------------------------------------------------
__global__ void zero_k() {
    int i = blockIdx.x * blockDim.x + threadIdx.x;
    int n = gridDim.x * blockDim.x;
    for (int j = i; j < 8192; j += n)    g_h1[j] = 0u;
    for (int j = i; j < 4*8192; j += n)  g_h2[j] = 0u;
    for (int j = i; j < 4*64; j += n)    g_h3[j] = 0u;
    for (int j = i; j < 32; j += n)      g_stats[j] = make_float2(0.f, 0.f);
}

__device__ __forceinline__ uint32_t f2tf(float f) {
    uint32_t r;
    asm("cvt.rna.tf32.f32 %0, %1;" : "=r"(r) : "f"(f));
    return r;
}
__device__ __forceinline__ void tf_split(float v, uint32_t& vb, uint32_t& vs) {
    vb = f2tf(v);
    vs = f2tf(v - __uint_as_float(vb));
}
__device__ __forceinline__ uint32_t bpack2(float v0, float v1, uint32_t& smw) {
    __nv_bfloat16 b0 = __float2bfloat16(v0), b1 = __float2bfloat16(v1);
    float r0 = v0 - __bfloat162float(b0);
    float r1 = v1 - __bfloat162float(b1);
    __nv_bfloat16 s0 = __float2bfloat16(r0), s1 = __float2bfloat16(r1);
    smw = (uint32_t)__bfloat16_as_ushort(s0) | ((uint32_t)__bfloat16_as_ushort(s1) << 16);
    return (uint32_t)__bfloat16_as_ushort(b0) | ((uint32_t)__bfloat16_as_ushort(b1) << 16);
}
__device__ __forceinline__ void mma16(float* d, const uint32_t* a, uint32_t b0, uint32_t b1) {
    asm("mma.sync.aligned.m16n8k16.row.col.f32.bf16.bf16.f32 "
        "{%0,%1,%2,%3}, {%4,%5,%6,%7}, {%8,%9}, {%0,%1,%2,%3};"
        : "+f"(d[0]), "+f"(d[1]), "+f"(d[2]), "+f"(d[3])
        : "r"(a[0]), "r"(a[1]), "r"(a[2]), "r"(a[3]), "r"(b0), "r"(b1));
}
__device__ __forceinline__ void mma4(float* d, uint32_t a0, uint32_t a1, uint32_t b0) {
    asm("mma.sync.aligned.m16n8k4.row.col.f32.tf32.tf32.f32 "
        "{%0,%1,%2,%3}, {%4,%5}, {%6}, {%0,%1,%2,%3};"
        : "+f"(d[0]), "+f"(d[1]), "+f"(d[2]), "+f"(d[3])
        : "r"(a0), "r"(a1), "r"(b0));
}
__device__ __forceinline__ float lrelu(float v) { return v >= 0.f ? v : 0.2f * v; }

__device__ __forceinline__ void cpasync8(uint32_t saddr, const void* gptr, bool ok) {
    int sz = ok ? 8 : 0;
    asm volatile("cp.async.ca.shared.global [%0], [%1], 8, %2;\n"
                 :: "r"(saddr), "l"(gptr), "r"(sz));
}

// ---------------------------------------------------------------------------
// Weight prep (layouts unchanged)
// ---------------------------------------------------------------------------
__global__ void prep_k(const float* __restrict__ w1, const float* __restrict__ w2,
                       const float* __restrict__ w3) {
    int i0 = blockIdx.x * blockDim.x + threadIdx.x;
    int n = gridDim.x * blockDim.x;
    for (int j = i0; j < 9*4*32; j += n) {
        int s = j / 128, k = (j >> 5) & 3, co = j & 31;
        tf_split(w1[co*36 + k*9 + s], g_w1b[j], g_w1s[j]);
    }
    for (int j = i0; j < 2*9*4*8*4; j += n) {
        int reg = j & 3, nq = (j >> 2) & 7, tt = (j >> 5) & 3;
        int s = (j >> 7) % 9, chunk = j / 1152;
        int co = nq + 8*(reg & 1);
        int pu = tt + 4*(reg >> 1);
        float v0 = w2[co*288 + (chunk*16 + pu)*9 + s];
        float v1 = w2[co*288 + (chunk*16 + pu + 8)*9 + s];
        uint32_t smw;
        uint32_t bg = bpack2(v0, v1, smw);
        g_w2b[j] = bg; g_w2s[j] = smw;
    }
    for (int j = i0; j < 9*4*8*4; j += n) {
        int reg = j & 3, nq = (j >> 2) & 7, tt = (j >> 5) & 3;
        int s = (j >> 7) % 9;
        int co = nq + 8*(reg & 1);
        int pu = tt + 4*(reg >> 1);
        float v0 = 0.f, v1 = 0.f;
        if (co < 8) {
            v0 = w3[co*144 + pu*9 + s];
            v1 = w3[co*144 + (pu + 8)*9 + s];
        }
        uint32_t smw;
        uint32_t bg = bpack2(v0, v1, smw);
        g_w3b[j] = bg; g_w3s[j] = smw;
    }
}

// ---------------------------------------------------------------------------
// conv1: 4 -> 32, leaky. Block 8 rows x 64 cols (r11 geometry, 2 CTAs/SM).
// ---------------------------------------------------------------------------
__global__ __launch_bounds__(256, 2)
void conv1_k(const float* __restrict__ in, const float* __restrict__ bias) {
    __shared__ uint2 t1[4*684];
    const int tid = threadIdx.x;
    const int wid = tid >> 5, lane = tid & 31;
    const int nq = lane >> 2, tt = lane & 3;
    const int x0 = blockIdx.x * 64, y0 = blockIdx.y * 8, b = blockIdx.z;

    for (int i = tid; i < 4*10*66; i += 256) {
        int c = i / 660, rem = i % 660;
        int yy = rem / 66, xx = rem % 66;
        int gy = y0 + yy - 1, gx = x0 + xx - 1;
        float v = 0.f;
        if (gy >= 0 && gy < H && gx >= 0 && gx < W)
            v = in[(((size_t)b*4 + c)*H + gy)*W + gx];
        uint32_t vb, vs;
        tf_split(v, vb, vs);
        t1[c*684 + yy*68 + xx] = make_uint2(vb, vs);
    }
    __syncthreads();

    float acc[2][8][4];
#pragma unroll
    for (int m = 0; m < 2; m++)
#pragma unroll
        for (int g = 0; g < 8; g++)
#pragma unroll
            for (int q = 0; q < 4; q++) acc[m][g][q] = 0.f;

#pragma unroll
    for (int s = 0; s < 9; s++) {
        const int kh = s / 3, kw = s % 3;
        int wb = (s*4 + tt)*32;
        uint32_t a0b = g_w1b[wb + nq],      a1b = g_w1b[wb + nq + 8];
        uint32_t a2b = g_w1b[wb + 16 + nq], a3b = g_w1b[wb + 24 + nq];
        uint32_t a0s = g_w1s[wb + nq],      a1s = g_w1s[wb + nq + 8];
        uint32_t a2s = g_w1s[wb + 16 + nq], a3s = g_w1s[wb + 24 + nq];
        int base = tt*684 + (wid + kh)*68 + nq + kw;
#pragma unroll
        for (int g = 0; g < 8; g++) {
            uint2 bv = t1[base + g*8];
            mma4(acc[0][g], a0b, a1b, bv.x);
            mma4(acc[0][g], a0s, a1s, bv.x);
            mma4(acc[0][g], a0b, a1b, bv.y);
            mma4(acc[1][g], a2b, a3b, bv.x);
            mma4(acc[1][g], a2s, a3s, bv.x);
            mma4(acc[1][g], a2b, a3b, bv.y);
        }
    }

    const int gy = y0 + wid;
#pragma unroll
    for (int m = 0; m < 2; m++) {
        int co0 = m*16 + nq;
        float b0 = bias[co0], b8 = bias[co0 + 8];
        size_t plane = (size_t)(b*16 + m*8 + nq);
#pragma unroll
        for (int g = 0; g < 8; g++) {
            int pe = x0 + g*8 + 2*tt;
            float v0 = lrelu(acc[m][g][0] + b0);
            float v1 = lrelu(acc[m][g][1] + b0);
            float v2 = lrelu(acc[m][g][2] + b8);
            float v3 = lrelu(acc[m][g][3] + b8);
            uint32_t se, so;
            uint32_t be = bpack2(v0, v2, se);
            uint32_t bo = bpack2(v1, v3, so);
            *(uint4*)&g_f1p[plane*PLANE + (size_t)gy*W + pe] = make_uint4(be, se, bo, so);
        }
    }
}

// ---------------------------------------------------------------------------
// conv2/conv3: bf16 m16n8k16, 16-row tile (r11 geometry), cp.async staging.
// ---------------------------------------------------------------------------
template<int CHUNKS, int COUT, bool LEAKY, bool PACKOUT>
__global__ __launch_bounds__(256, 2)
void convP_k(const uint2* __restrict__ inp, const uint4* __restrict__ wb4,
             const uint4* __restrict__ ws4, const float* __restrict__ bias,
             uint2* __restrict__ outp, float* __restrict__ outf) {
    extern __shared__ uint2 tile[];   // [1188*8]
    const int tid = threadIdx.x;
    const int wid = tid >> 5, lane = tid & 31;
    const int nq = lane >> 2, tt = lane & 3;
    const int x0 = blockIdx.x * 64, y0 = blockIdx.y * 16, b = blockIdx.z;
    const uint32_t smem_base = (uint32_t)__cvta_generic_to_shared(tile);

    float acc[16][4];
#pragma unroll
    for (int g = 0; g < 16; g++)
#pragma unroll
        for (int q = 0; q < 4; q++) acc[g][q] = 0.f;

#pragma unroll 1
    for (int chunk = 0; chunk < CHUNKS; chunk++) {
        __syncthreads();
        for (int i = tid; i < 8*1188; i += 256) {
            int u = i / 1188, pix = i - u*1188;
            int yy = pix / 66, xx = pix - yy*66;
            int gy = y0 + yy - 1, gx = x0 + xx - 1;
            bool ok = (gy >= 0 && gy < H && gx >= 0 && gx < W);
            const uint2* src = ok
                ? &inp[(((size_t)b*CHUNKS + chunk)*8 + u)*PLANE + (size_t)gy*W + gx]
                : inp;
            int rr = (pix + (pix >> 2)) & 3;
            int pos = 2*(((u & 3) + rr) & 3) + (u >> 2);
            cpasync8(smem_base + (uint32_t)(pix*8 + pos)*8u, src, ok);
        }
        asm volatile("cp.async.commit_group;\n");
        asm volatile("cp.async.wait_group 0;\n");
        __syncthreads();

#pragma unroll
        for (int s = 0; s < 9; s++) {
            const int kh = s / 3, kw = s % 3;
            uint4 A = wb4[((chunk*9 + s)*4 + tt)*8 + nq];
            uint4 S = ws4[((chunk*9 + s)*4 + tt)*8 + nq];
            uint32_t ab[4]  = {A.x, A.y, A.z, A.w};
            uint32_t as_[4] = {S.x, S.y, S.z, S.w};
#pragma unroll
            for (int g = 0; g < 16; g++) {
                int ty = 2*wid + (g >> 3) + kh;
                int tx = (g & 7)*8 + nq + kw;
                int pix = ty*66 + tx;
                int rr = (pix + (pix >> 2)) & 3;
                int t = pix*8 + 2*((tt + rr) & 3);
                uint4 Bv = *(const uint4*)&tile[t];
                mma16(acc[g], ab,  Bv.x, Bv.z);
                mma16(acc[g], as_, Bv.x, Bv.z);
                mma16(acc[g], ab,  Bv.y, Bv.w);
            }
        }
    }

    if (PACKOUT) {
        float b0 = bias[nq], b8 = bias[nq + 8];
        size_t plane = (size_t)(b*8 + nq);
#pragma unroll
        for (int g = 0; g < 16; g++) {
            int gy = y0 + 2*wid + (g >> 3);
            int pe = x0 + (g & 7)*8 + 2*tt;
            float v0 = acc[g][0] + b0, v1 = acc[g][1] + b0;
            float v2 = acc[g][2] + b8, v3 = acc[g][3] + b8;
            if (LEAKY) { v0 = lrelu(v0); v1 = lrelu(v1); v2 = lrelu(v2); v3 = lrelu(v3); }
            uint32_t se, so;
            uint32_t be = bpack2(v0, v2, se);
            uint32_t bo = bpack2(v1, v3, so);
            *(uint4*)&outp[plane*PLANE + (size_t)gy*W + pe] = make_uint4(be, se, bo, so);
        }
    } else {
        float b0 = bias[nq];
#pragma unroll
        for (int g = 0; g < 16; g++) {
            int gy = y0 + 2*wid + (g >> 3);
            int pe = x0 + (g & 7)*8 + 2*tt;
            float2 o0;
            o0.x = acc[g][0] + b0; o0.y = acc[g][1] + b0;
            if (LEAKY) { o0.x = lrelu(o0.x); o0.y = lrelu(o0.y); }
            *(float2*)&outf[(((size_t)b*COUT + nq)*H + gy)*W + pe] = o0;
        }
    }
}

// ---------------------------------------------------------------------------
// Multi-scale box std maps (unchanged)
// ---------------------------------------------------------------------------
__device__ __forceinline__ int refl(int i) {
    return i < 0 ? -i : (i > H - 1 ? 2*(H - 1) - i : i);
}

__global__ __launch_bounds__(512)
void boxstd_k() {
    constexpr int ROWS = 64;
    extern __shared__ float bsm[];
    float* csA  = bsm;
    float* csB  = bsm + 4096;
    float* pref = bsm + 8192;

    const int j    = threadIdx.x;
    const int lane = j & 31;
    const int wid  = j >> 5;
    const int strip = blockIdx.x;
    const int scale = blockIdx.y;
    const int b     = blockIdx.z;

    const int K = (scale == 0) ? 11 : (scale == 1) ? 25 : 49;
    const int P = K >> 1;
    const float inv = 1.f / (float)(K * K);
    const int r0 = strip * ROWS;

    for (int c = 0; c < 8; c++) {
        const float* fp = g_f + ((size_t)(b*8 + c)) * PLANE;
        float s = 0.f, s2 = 0.f;
        for (int i = r0 - P; i <= r0 + P; i++) {
            float v = fp[refl(i)*W + j];
            s += v;
            s2 = fmaf(v, v, s2);
        }
        csA[c*512 + j] = s;
        csB[c*512 + j] = s2;
    }

    const int sc = wid & 7, sq = wid >> 3;
    float* src = (sq ? csB : csA) + sc*512;
    float* pr  = pref + wid*513;

    for (int r = r0; r < r0 + ROWS; r++) {
        if (r > r0) {
            int ra = refl(r + P), rs = refl(r - 1 - P);
#pragma unroll
            for (int c = 0; c < 8; c++) {
                const float* fp = g_f + ((size_t)(b*8 + c)) * PLANE;
                float va = fp[ra*W + j], vs = fp[rs*W + j];
                csA[c*512 + j] += va - vs;
                csB[c*512 + j] += va*va - vs*vs;
            }
        }
        __syncthreads();

        {
            float seg[16];
            float run = 0.f;
            int base = lane * 16;
#pragma unroll
            for (int i = 0; i < 16; i++) { run += src[base + i]; seg[i] = run; }
            float v = run;
#pragma unroll
            for (int d = 1; d < 32; d <<= 1) {
                float t = __shfl_up_sync(0xffffffffu, v, d);
                if (lane >= d) v += t;
            }
            float carry = v - run;
#pragma unroll
            for (int i = 0; i < 16; i++) pr[base + 1 + i] = seg[i] + carry;
            if (lane == 0) pr[0] = 0.f;
        }
        __syncthreads();

        const int lo = j - P, hi = j + P;
        const int loC = max(lo, 0), hiC = min(hi, W - 1);
        float rowacc = 0.f;
#pragma unroll
        for (int c = 0; c < 8; c++) {
            const float* pA = pref + c*513;
            const float* pB = pref + (8 + c)*513;
            float Sx = pA[hiC + 1] - pA[loC];
            float Sy = pB[hiC + 1] - pB[loC];
            if (lo < 0) {
                Sx += pA[-lo + 1] - pA[1];
                Sy += pB[-lo + 1] - pB[1];
            }
            if (hi > W - 1) {
                Sx += pA[W - 1] - pA[2*(W - 1) - hi];
                Sy += pB[W - 1] - pB[2*(W - 1) - hi];
            }
            float m  = Sx * inv;
            float m2 = Sy * inv;
            rowacc += sqrtf(fmaxf(m2 - m*m, 1e-6f));
        }
        g_maps[(size_t)scale*NPIX + ((size_t)b*H + r)*W + j] =
            powf(rowacc * 0.125f, 0.8f);
    }
}

// ---------------------------------------------------------------------------
// Fusion + level-1 histogram
// ---------------------------------------------------------------------------
__global__ void fuse_hist1_k(const float* __restrict__ fw, const float* __restrict__ fb) {
    __shared__ unsigned h[8192];
    for (int i = threadIdx.x; i < 8192; i += blockDim.x) h[i] = 0u;
    __syncthreads();
    const float w0 = fw[0], w1 = fw[1], w2 = fw[2], b0 = fb[0];
    const size_t N = NPIX;
    for (size_t i = (size_t)blockIdx.x*blockDim.x + threadIdx.x; i < N;
         i += (size_t)gridDim.x*blockDim.x) {
        float v = w0*g_maps[i] + w1*g_maps[i + N] + w2*g_maps[i + 2*N] + b0;
        v = fmaxf(v, 0.f);
        g_fused[i] = v;
        atomicAdd(&h[__float_as_uint(v) >> 19], 1u);
    }
    __syncthreads();
    for (int i = threadIdx.x; i < 8192; i += blockDim.x)
        if (h[i]) atomicAdd(&g_h1[i], h[i]);
}

__device__ void findRank(const unsigned* __restrict__ hist, int nbins, unsigned rank,
                         unsigned* sbin, unsigned* srem,
                         unsigned* sp, unsigned* sb) {
    __syncthreads();
    const int tid = threadIdx.x;
    const int chunk = nbins / 256;
    unsigned loc = 0;
    for (int i = 0; i < chunk; i++) loc += hist[tid*chunk + i];
    sp[tid] = loc;
    __syncthreads();
    if (tid == 0) {
        unsigned c = 0;
        for (int i = 0; i < 256; i++) { sb[i] = c; c += sp[i]; }
    }
    __syncthreads();
    unsigned cum = sb[tid];
    for (int i = 0; i < chunk; i++) {
        unsigned cnt = hist[tid*chunk + i];
        if (rank >= cum && rank < cum + cnt) { *sbin = tid*chunk + i; *srem = rank - cum; }
        cum += cnt;
    }
    __syncthreads();
}

__global__ void scan1_k() {
    __shared__ unsigned sp[256], sb[256];
    __shared__ unsigned rbin, rrem;
    const unsigned ranks[4] = {524287u, 524288u, 1572863u, 1572864u};
    for (int r = 0; r < 4; r++) {
        findRank(g_h1, 8192, ranks[r], &rbin, &rrem, sp, sb);
        if (threadIdx.x == 0) { g_qs.pref1[r] = rbin; g_qs.rem[r] = rrem; }
        __syncthreads();
    }
}

__global__ void hist2_k() {
    extern __shared__ unsigned h2s[];   // 4*8192
    for (int i = threadIdx.x; i < 4*8192; i += blockDim.x) h2s[i] = 0u;
    __syncthreads();
    unsigned p0 = g_qs.pref1[0], p1 = g_qs.pref1[1];
    unsigned p2 = g_qs.pref1[2], p3 = g_qs.pref1[3];
    const uint4* fp = (const uint4*)g_fused;
    const size_t N4 = NPIX/4;
    for (size_t i = (size_t)blockIdx.x*blockDim.x + threadIdx.x; i < N4;
         i += (size_t)gridDim.x*blockDim.x) {
        uint4 v = fp[i];
        uint32_t bb[4] = {v.x, v.y, v.z, v.w};
#pragma unroll
        for (int e = 0; e < 4; e++) {
            unsigned hi = bb[e] >> 19, mid = (bb[e] >> 6) & 8191u;
            if (hi == p0) atomicAdd(&h2s[mid], 1u);
            if (hi == p1) atomicAdd(&h2s[8192 + mid], 1u);
            if (hi == p2) atomicAdd(&h2s[16384 + mid], 1u);
            if (hi == p3) atomicAdd(&h2s[24576 + mid], 1u);
        }
    }
    __syncthreads();
    for (int i = threadIdx.x; i < 4*8192; i += blockDim.x)
        if (h2s[i]) atomicAdd(&g_h2[i], h2s[i]);
}

__global__ void scan2_k() {
    __shared__ unsigned sp[256], sb[256];
    __shared__ unsigned rbin, rrem;
    for (int r = 0; r < 4; r++) {
        unsigned rank = g_qs.rem[r];
        findRank(g_h2 + r*8192, 8192, rank, &rbin, &rrem, sp, sb);
        if (threadIdx.x == 0) {
            g_qs.pref2[r] = (g_qs.pref1[r] << 13) | rbin;
            g_qs.rem[r]   = rrem;
        }
        __syncthreads();
    }
}

__global__ void hist3_k() {
    __shared__ unsigned h[4*64];
    for (int i = threadIdx.x; i < 4*64; i += blockDim.x) h[i] = 0u;
    __syncthreads();
    unsigned p0 = g_qs.pref2[0], p1 = g_qs.pref2[1];
    unsigned p2 = g_qs.pref2[2], p3 = g_qs.pref2[3];
    const uint4* fp = (const uint4*)g_fused;
    const size_t N4 = NPIX/4;
    for (size_t i = (size_t)blockIdx.x*blockDim.x + threadIdx.x; i < N4;
         i += (size_t)gridDim.x*blockDim.x) {
        uint4 v = fp[i];
        uint32_t bb[4] = {v.x, v.y, v.z, v.w};
#pragma unroll
        for (int e = 0; e < 4; e++) {
            unsigned hi = bb[e] >> 6, lo = bb[e] & 63u;
            if (hi == p0) atomicAdd(&h[lo], 1u);
            if (hi == p1) atomicAdd(&h[64 + lo], 1u);
            if (hi == p2) atomicAdd(&h[128 + lo], 1u);
            if (hi == p3) atomicAdd(&h[192 + lo], 1u);
        }
    }
    __syncthreads();
    for (int i = threadIdx.x; i < 4*64; i += blockDim.x)
        if (h[i]) atomicAdd(&g_h3[i], h[i]);
}

__global__ void scan3_k() {
    __shared__ float sv[4];
    const int r = threadIdx.x;
    if (r < 4) {
        unsigned rank = g_qs.rem[r];
        unsigned cum = 0, bin = 0;
        for (int i = 0; i < 64; i++) {
            unsigned c = g_h3[r*64 + i];
            if (rank >= cum && rank < cum + c) bin = (unsigned)i;
            cum += c;
        }
        sv[r] = __uint_as_float((g_qs.pref2[r] << 6) | bin);
    }
    __syncthreads();
    if (r == 0) {
        float q25 = sv[0] + 0.75f*(sv[1] - sv[0]);
        float q75 = sv[2] + 0.25f*(sv[3] - sv[2]);
        float iqr = q75 - q25;
        if (iqr < 1e-5f) iqr = 0.05f;
        g_qs.q25 = q25; g_qs.q75 = q75; g_qs.iqr = iqr;
    }
}

__global__ void xstats_k(const float* __restrict__ x) {
    const int bc = blockIdx.x;
    const int sl = blockIdx.y;
    const float* p = x + ((size_t)bc << 18) + (size_t)sl * 32768;
    float s = 0.f, s2 = 0.f;
    for (int i = threadIdx.x; i < 32768; i += 256) {
        float v = p[i];
        s += v;
        s2 = fmaf(v, v, s2);
    }
#pragma unroll
    for (int o = 16; o; o >>= 1) {
        s  += __shfl_xor_sync(0xffffffffu, s, o);
        s2 += __shfl_xor_sync(0xffffffffu, s2, o);
    }
    __shared__ float ss[8], ss2[8];
    int w = threadIdx.x >> 5, l = threadIdx.x & 31;
    if (l == 0) { ss[w] = s; ss2[w] = s2; }
    __syncthreads();
    if (threadIdx.x == 0) {
        float a = 0.f, a2 = 0.f;
        for (int i = 0; i < 8; i++) { a += ss[i]; a2 += ss2[i]; }
        atomicAdd(&g_stats[bc].x, a);
        atomicAdd(&g_stats[bc].y, a2);
    }
}

__global__ void thr_k(const float* __restrict__ chw) {
    const int t = threadIdx.x;
    const int c = t & 3;
    float w0 = chw[0], w1 = chw[1], w2 = chw[2], w3 = chw[3];
    float mx = fmaxf(fmaxf(w0, w1), fmaxf(w2, w3));
    float e0 = expf(w0 - mx), e1 = expf(w1 - mx), e2 = expf(w2 - mx), e3 = expf(w3 - mx);
    float se = e0 + e1 + e2 + e3;
    float cw = ((c == 0) ? e0 : (c == 1) ? e1 : (c == 2) ? e2 : e3) / se;

    float2 st = g_stats[t];
    const float N = (float)PLANE;
    float var = (st.y - st.x*st.x/N) / (N - 1.f);
    float gstd = sqrtf(fmaxf(var, 0.f));

    float q25 = g_qs.q25, q75 = g_qs.q75, iqr = g_qs.iqr;
    float lower = q25 - 0.5f*iqr;
    float upper = q75 + 0.5f*iqr;
    float gf = fminf(fmaxf(gstd*5.f, 0.5f), 2.f);
    lower *= gf; upper *= gf;
    float cf = fminf(fmaxf(cw*gstd*2.f, 0.8f), 1.2f);
    lower *= cf; upper *= cf;

    float d = fabsf(upper - lower);
#pragma unroll
    for (int o = 16; o; o >>= 1) d = fminf(d, __shfl_xor_sync(0xffffffffu, d, o));
    if (d < 1e-5f) {
        float mt = 0.5f*(upper + lower);
        lower = mt - 0.05f;
        upper = mt + 0.05f;
    }
    g_thr[t]      = lower;
    g_thr[32 + t] = fmaxf(upper - lower, 1e-5f);
}

__global__ void mask_k(float* __restrict__ out) {
    for (size_t i = (size_t)blockIdx.x*blockDim.x + threadIdx.x; i < (size_t)NPIX;
         i += (size_t)gridDim.x*blockDim.x) {
        int b = (int)(i >> 18);
        float v = g_fused[i];
        float acc = 0.f;
#pragma unroll
        for (int c = 0; c < 4; c++) {
            float lo  = g_thr[b*4 + c];
            float dif = g_thr[32 + b*4 + c];
            float nrm = fminf(fmaxf((v - lo)/dif, 0.f), 1.f);
            acc += 1.f/(1.f + expf(3.f - 6.f*nrm));
        }
        out[i] = 0.25f*acc;
    }
}

// ---------------------------------------------------------------------------
// Launch
// ---------------------------------------------------------------------------
extern "C" void kernel_launch(void* const* d_in, const int* in_sizes, int n_in,
                              void* d_out, int out_size) {
    const float* x        = (const float*)d_in[0];
    const float* conv1_w  = (const float*)d_in[1];
    const float* conv1_b  = (const float*)d_in[2];
    const float* conv2_w  = (const float*)d_in[3];
    const float* conv2_b  = (const float*)d_in[4];
    const float* conv3_w  = (const float*)d_in[5];
    const float* conv3_b  = (const float*)d_in[6];
    const float* fusion_w = (const float*)d_in[7];
    const float* fusion_b = (const float*)d_in[8];
    const float* chw      = (const float*)d_in[9];
    float* out = (float*)d_out;

    uint2* f1p; cudaGetSymbolAddress((void**)&f1p, g_f1p);
    uint2* f2p; cudaGetSymbolAddress((void**)&f2p, g_f2p);
    float* f  ; cudaGetSymbolAddress((void**)&f  , g_f);
    uint4 *w2b, *w2s, *w3b, *w3s;
    cudaGetSymbolAddress((void**)&w2b, g_w2b);
    cudaGetSymbolAddress((void**)&w2s, g_w2s);
    cudaGetSymbolAddress((void**)&w3b, g_w3b);
    cudaGetSymbolAddress((void**)&w3s, g_w3s);

    const int smemP  = 1188 * 8 * 8;                 // 76032
    const int smemBX = (4096 + 4096 + 16*513) * 4;   // 65668
    const int smemH2 = 4 * 8192 * 4;                 // 131072
    cudaFuncSetAttribute(convP_k<2, 16, true, true>,  cudaFuncAttributeMaxDynamicSharedMemorySize, smemP);
    cudaFuncSetAttribute(convP_k<1, 8, false, false>, cudaFuncAttributeMaxDynamicSharedMemorySize, smemP);
    cudaFuncSetAttribute(boxstd_k, cudaFuncAttributeMaxDynamicSharedMemorySize, smemBX);
    cudaFuncSetAttribute(hist2_k,  cudaFuncAttributeMaxDynamicSharedMemorySize, smemH2);

    zero_k<<<64, 256>>>();
    prep_k<<<16, 256>>>(conv1_w, conv2_w, conv3_w);

    conv1_k<<<dim3(W/64, H/8, B), 256>>>(x, conv1_b);
    convP_k<2, 16, true, true><<<dim3(W/64, H/16, B), 256, smemP>>>(f1p, w2b, w2s, conv2_b, f2p, 0);
    convP_k<1, 8, false, false><<<dim3(W/64, H/16, B), 256, smemP>>>(f2p, w3b, w3s, conv3_b, 0, f);

    boxstd_k<<<dim3(H/64, 3, B), 512, smemBX>>>();

    fuse_hist1_k<<<448, 256>>>(fusion_w, fusion_b);
    scan1_k<<<1, 256>>>();
    hist2_k<<<148, 512, smemH2>>>();
    scan2_k<<<1, 256>>>();
    hist3_k<<<256, 256>>>();
    scan3_k<<<1, 32>>>();

    xstats_k<<<dim3(32, 8), 256>>>(x);
    thr_k<<<1, 32>>>(chw);

    mask_k<<<1024, 256>>>(out);
}

// round 15
// speedup vs baseline: 1.1009x; 1.0351x over previous
#include <cuda_runtime.h>
#include <cuda_bf16.h>
#include <math.h>
#include <stdint.h>

#define B  8
#define H  512
#define W  512
#define PLANE (H*W)
#define NPIX (B*PLANE)

// ---------------------------------------------------------------------------
// Scratch
// ---------------------------------------------------------------------------
__device__ __align__(16) uint2 g_f1p[(size_t)B*16*PLANE]; // packed split pairs (c, c+8)
__device__ __align__(16) uint2 g_f2p[(size_t)B* 8*PLANE];
__device__ float g_f [(size_t)B*8*PLANE];
__device__ float g_maps[(size_t)3*NPIX];
__device__ float g_fused[(size_t)NPIX];
__device__ unsigned g_h1[8192];
__device__ unsigned g_h2[4*8192];
__device__ unsigned g_h3[4*64];
__device__ float2 g_stats[32];
__device__ float g_thr[64];

__device__ uint32_t g_w1b[9*4*32], g_w1s[9*4*32];          // [s][k4][co32]
__device__ __align__(16) uint32_t g_w2b[2*9*4*8*4], g_w2s[2*9*4*8*4];
__device__ __align__(16) uint32_t g_w3b[9*4*8*4],   g_w3s[9*4*8*4];

struct QState {
    unsigned pref1[4];
    unsigned rem[4];
    unsigned pref2[4];
    float q25, q75, iqr;
};
__device__ QState g_qs;

// ---------------------------------------------------------------------------
__device__ __forceinline__ uint32_t f2tf(float f) {
    uint32_t r;
    asm("cvt.rna.tf32.f32 %0, %1;" : "=r"(r) : "f"(f));
    return r;
}
__device__ __forceinline__ void tf_split(float v, uint32_t& vb, uint32_t& vs) {
    vb = f2tf(v);
    vs = f2tf(v - __uint_as_float(vb));
}
__device__ __forceinline__ uint32_t bpack2(float v0, float v1, uint32_t& smw) {
    __nv_bfloat16 b0 = __float2bfloat16(v0), b1 = __float2bfloat16(v1);
    float r0 = v0 - __bfloat162float(b0);
    float r1 = v1 - __bfloat162float(b1);
    __nv_bfloat16 s0 = __float2bfloat16(r0), s1 = __float2bfloat16(r1);
    smw = (uint32_t)__bfloat16_as_ushort(s0) | ((uint32_t)__bfloat16_as_ushort(s1) << 16);
    return (uint32_t)__bfloat16_as_ushort(b0) | ((uint32_t)__bfloat16_as_ushort(b1) << 16);
}
__device__ __forceinline__ void mma16(float* d, const uint32_t* a, uint32_t b0, uint32_t b1) {
    asm("mma.sync.aligned.m16n8k16.row.col.f32.bf16.bf16.f32 "
        "{%0,%1,%2,%3}, {%4,%5,%6,%7}, {%8,%9}, {%0,%1,%2,%3};"
        : "+f"(d[0]), "+f"(d[1]), "+f"(d[2]), "+f"(d[3])
        : "r"(a[0]), "r"(a[1]), "r"(a[2]), "r"(a[3]), "r"(b0), "r"(b1));
}
__device__ __forceinline__ void mma4(float* d, uint32_t a0, uint32_t a1, uint32_t b0) {
    asm("mma.sync.aligned.m16n8k4.row.col.f32.tf32.tf32.f32 "
        "{%0,%1,%2,%3}, {%4,%5}, {%6}, {%0,%1,%2,%3};"
        : "+f"(d[0]), "+f"(d[1]), "+f"(d[2]), "+f"(d[3])
        : "r"(a0), "r"(a1), "r"(b0));
}
__device__ __forceinline__ float lrelu(float v) { return v >= 0.f ? v : 0.2f * v; }

__device__ __forceinline__ void cpasync8(uint32_t saddr, const void* gptr, bool ok) {
    int sz = ok ? 8 : 0;
    asm volatile("cp.async.ca.shared.global [%0], [%1], 8, %2;\n"
                 :: "r"(saddr), "l"(gptr), "r"(sz));
}

// ---------------------------------------------------------------------------
// Weight prep + accumulator zeroing (fused)
// ---------------------------------------------------------------------------
__global__ void prep_k(const float* __restrict__ w1, const float* __restrict__ w2,
                       const float* __restrict__ w3) {
    int i0 = blockIdx.x * blockDim.x + threadIdx.x;
    int n = gridDim.x * blockDim.x;
    for (int j = i0; j < 8192; j += n)    g_h1[j] = 0u;
    for (int j = i0; j < 4*8192; j += n)  g_h2[j] = 0u;
    for (int j = i0; j < 4*64; j += n)    g_h3[j] = 0u;
    for (int j = i0; j < 32; j += n)      g_stats[j] = make_float2(0.f, 0.f);

    for (int j = i0; j < 9*4*32; j += n) {
        int s = j / 128, k = (j >> 5) & 3, co = j & 31;
        tf_split(w1[co*36 + k*9 + s], g_w1b[j], g_w1s[j]);
    }
    for (int j = i0; j < 2*9*4*8*4; j += n) {
        int reg = j & 3, nq = (j >> 2) & 7, tt = (j >> 5) & 3;
        int s = (j >> 7) % 9, chunk = j / 1152;
        int co = nq + 8*(reg & 1);
        int pu = tt + 4*(reg >> 1);
        float v0 = w2[co*288 + (chunk*16 + pu)*9 + s];
        float v1 = w2[co*288 + (chunk*16 + pu + 8)*9 + s];
        uint32_t smw;
        uint32_t bg = bpack2(v0, v1, smw);
        g_w2b[j] = bg; g_w2s[j] = smw;
    }
    for (int j = i0; j < 9*4*8*4; j += n) {
        int reg = j & 3, nq = (j >> 2) & 7, tt = (j >> 5) & 3;
        int s = (j >> 7) % 9;
        int co = nq + 8*(reg & 1);
        int pu = tt + 4*(reg >> 1);
        float v0 = 0.f, v1 = 0.f;
        if (co < 8) {
            v0 = w3[co*144 + pu*9 + s];
            v1 = w3[co*144 + (pu + 8)*9 + s];
        }
        uint32_t smw;
        uint32_t bg = bpack2(v0, v1, smw);
        g_w3b[j] = bg; g_w3s[j] = smw;
    }
}

// ---------------------------------------------------------------------------
// conv1: 4 -> 32, leaky. Block 8 rows x 64 cols, 2 CTAs/SM.
// ---------------------------------------------------------------------------
__global__ __launch_bounds__(256, 2)
void conv1_k(const float* __restrict__ in, const float* __restrict__ bias) {
    __shared__ uint2 t1[4*684];
    const int tid = threadIdx.x;
    const int wid = tid >> 5, lane = tid & 31;
    const int nq = lane >> 2, tt = lane & 3;
    const int x0 = blockIdx.x * 64, y0 = blockIdx.y * 8, b = blockIdx.z;

    for (int i = tid; i < 4*10*66; i += 256) {
        int c = i / 660, rem = i % 660;
        int yy = rem / 66, xx = rem % 66;
        int gy = y0 + yy - 1, gx = x0 + xx - 1;
        float v = 0.f;
        if (gy >= 0 && gy < H && gx >= 0 && gx < W)
            v = in[(((size_t)b*4 + c)*H + gy)*W + gx];
        uint32_t vb, vs;
        tf_split(v, vb, vs);
        t1[c*684 + yy*68 + xx] = make_uint2(vb, vs);
    }
    __syncthreads();

    float acc[2][8][4];
#pragma unroll
    for (int m = 0; m < 2; m++)
#pragma unroll
        for (int g = 0; g < 8; g++)
#pragma unroll
            for (int q = 0; q < 4; q++) acc[m][g][q] = 0.f;

#pragma unroll
    for (int s = 0; s < 9; s++) {
        const int kh = s / 3, kw = s % 3;
        int wb = (s*4 + tt)*32;
        uint32_t a0b = g_w1b[wb + nq],      a1b = g_w1b[wb + nq + 8];
        uint32_t a2b = g_w1b[wb + 16 + nq], a3b = g_w1b[wb + 24 + nq];
        uint32_t a0s = g_w1s[wb + nq],      a1s = g_w1s[wb + nq + 8];
        uint32_t a2s = g_w1s[wb + 16 + nq], a3s = g_w1s[wb + 24 + nq];
        int base = tt*684 + (wid + kh)*68 + nq + kw;
#pragma unroll
        for (int g = 0; g < 8; g++) {
            uint2 bv = t1[base + g*8];
            mma4(acc[0][g], a0b, a1b, bv.x);
            mma4(acc[0][g], a0s, a1s, bv.x);
            mma4(acc[0][g], a0b, a1b, bv.y);
            mma4(acc[1][g], a2b, a3b, bv.x);
            mma4(acc[1][g], a2s, a3s, bv.x);
            mma4(acc[1][g], a2b, a3b, bv.y);
        }
    }

    const int gy = y0 + wid;
#pragma unroll
    for (int m = 0; m < 2; m++) {
        int co0 = m*16 + nq;
        float b0 = bias[co0], b8 = bias[co0 + 8];
        size_t plane = (size_t)(b*16 + m*8 + nq);
#pragma unroll
        for (int g = 0; g < 8; g++) {
            int pe = x0 + g*8 + 2*tt;
            float v0 = lrelu(acc[m][g][0] + b0);
            float v1 = lrelu(acc[m][g][1] + b0);
            float v2 = lrelu(acc[m][g][2] + b8);
            float v3 = lrelu(acc[m][g][3] + b8);
            uint32_t se, so;
            uint32_t be = bpack2(v0, v2, se);
            uint32_t bo = bpack2(v1, v3, so);
            *(uint4*)&g_f1p[plane*PLANE + (size_t)gy*W + pe] = make_uint4(be, se, bo, so);
        }
    }
}

// ---------------------------------------------------------------------------
// conv2/conv3: bf16 m16n8k16, cp.async staging, incremental swizzled address.
// Identity: pix += 8  ==>  t = (t + 64) ^ 4  (slot = 2*((tt+rr)&3), rr += 2 mod 4)
// ---------------------------------------------------------------------------
template<int CHUNKS, int COUT, bool LEAKY, bool PACKOUT>
__global__ __launch_bounds__(256, 2)
void convP_k(const uint2* __restrict__ inp, const uint4* __restrict__ wb4,
             const uint4* __restrict__ ws4, const float* __restrict__ bias,
             uint2* __restrict__ outp, float* __restrict__ outf) {
    extern __shared__ uint2 tile[];   // [1188*8]
    const int tid = threadIdx.x;
    const int wid = tid >> 5, lane = tid & 31;
    const int nq = lane >> 2, tt = lane & 3;
    const int x0 = blockIdx.x * 64, y0 = blockIdx.y * 16, b = blockIdx.z;
    const uint32_t smem_base = (uint32_t)__cvta_generic_to_shared(tile);

    float acc[16][4];
#pragma unroll
    for (int g = 0; g < 16; g++)
#pragma unroll
        for (int q = 0; q < 4; q++) acc[g][q] = 0.f;

#pragma unroll 1
    for (int chunk = 0; chunk < CHUNKS; chunk++) {
        __syncthreads();
        for (int i = tid; i < 8*1188; i += 256) {
            int u = i / 1188, pix = i - u*1188;
            int yy = pix / 66, xx = pix - yy*66;
            int gy = y0 + yy - 1, gx = x0 + xx - 1;
            bool ok = (gy >= 0 && gy < H && gx >= 0 && gx < W);
            const uint2* src = ok
                ? &inp[(((size_t)b*CHUNKS + chunk)*8 + u)*PLANE + (size_t)gy*W + gx]
                : inp;
            int rr = (pix + (pix >> 2)) & 3;
            int pos = 2*(((u & 3) + rr) & 3) + (u >> 2);
            cpasync8(smem_base + (uint32_t)(pix*8 + pos)*8u, src, ok);
        }
        asm volatile("cp.async.commit_group;\n");
        asm volatile("cp.async.wait_group 0;\n");
        __syncthreads();

#pragma unroll
        for (int s = 0; s < 9; s++) {
            const int kh = s / 3, kw = s % 3;
            uint4 A = wb4[((chunk*9 + s)*4 + tt)*8 + nq];
            uint4 S = ws4[((chunk*9 + s)*4 + tt)*8 + nq];
            uint32_t ab[4]  = {A.x, A.y, A.z, A.w};
            uint32_t as_[4] = {S.x, S.y, S.z, S.w};

            int pix0 = (2*wid + kh)*66 + nq + kw;
            int rr0 = (pix0 + (pix0 >> 2)) & 3;
            int t0 = pix0*8 + 2*((tt + rr0) & 3);
            int pix1 = pix0 + 66;
            int rr1 = (pix1 + (pix1 >> 2)) & 3;
            int t1 = pix1*8 + 2*((tt + rr1) & 3);
#pragma unroll
            for (int gg = 0; gg < 8; gg++) {
                uint4 Bv0 = *(const uint4*)&tile[t0];
                mma16(acc[gg], ab,  Bv0.x, Bv0.z);
                mma16(acc[gg], as_, Bv0.x, Bv0.z);
                mma16(acc[gg], ab,  Bv0.y, Bv0.w);
                uint4 Bv1 = *(const uint4*)&tile[t1];
                mma16(acc[8+gg], ab,  Bv1.x, Bv1.z);
                mma16(acc[8+gg], as_, Bv1.x, Bv1.z);
                mma16(acc[8+gg], ab,  Bv1.y, Bv1.w);
                t0 = (t0 + 64) ^ 4;
                t1 = (t1 + 64) ^ 4;
            }
        }
    }

    if (PACKOUT) {
        float b0 = bias[nq], b8 = bias[nq + 8];
        size_t plane = (size_t)(b*8 + nq);
#pragma unroll
        for (int g = 0; g < 16; g++) {
            int gy = y0 + 2*wid + (g >> 3);
            int pe = x0 + (g & 7)*8 + 2*tt;
            float v0 = acc[g][0] + b0, v1 = acc[g][1] + b0;
            float v2 = acc[g][2] + b8, v3 = acc[g][3] + b8;
            if (LEAKY) { v0 = lrelu(v0); v1 = lrelu(v1); v2 = lrelu(v2); v3 = lrelu(v3); }
            uint32_t se, so;
            uint32_t be = bpack2(v0, v2, se);
            uint32_t bo = bpack2(v1, v3, so);
            *(uint4*)&outp[plane*PLANE + (size_t)gy*W + pe] = make_uint4(be, se, bo, so);
        }
    } else {
        float b0 = bias[nq];
#pragma unroll
        for (int g = 0; g < 16; g++) {
            int gy = y0 + 2*wid + (g >> 3);
            int pe = x0 + (g & 7)*8 + 2*tt;
            float2 o0;
            o0.x = acc[g][0] + b0; o0.y = acc[g][1] + b0;
            if (LEAKY) { o0.x = lrelu(o0.x); o0.y = lrelu(o0.y); }
            *(float2*)&outf[(((size_t)b*COUT + nq)*H + gy)*W + pe] = o0;
        }
    }
}

// ---------------------------------------------------------------------------
// Multi-scale box std maps — software-pipelined row updates
// ---------------------------------------------------------------------------
__device__ __forceinline__ int refl(int i) {
    return i < 0 ? -i : (i > H - 1 ? 2*(H - 1) - i : i);
}

__global__ __launch_bounds__(512)
void boxstd_k() {
    constexpr int ROWS = 64;
    extern __shared__ float bsm[];
    float* csA  = bsm;
    float* csB  = bsm + 4096;
    float* pref = bsm + 8192;

    const int j    = threadIdx.x;
    const int lane = j & 31;
    const int wid  = j >> 5;
    const int strip = blockIdx.x;
    const int scale = blockIdx.y;
    const int b     = blockIdx.z;

    const int K = (scale == 0) ? 11 : (scale == 1) ? 25 : 49;
    const int P = K >> 1;
    const float inv = 1.f / (float)(K * K);
    const int r0 = strip * ROWS;

    for (int c = 0; c < 8; c++) {
        const float* fp = g_f + ((size_t)(b*8 + c)) * PLANE;
        float s = 0.f, s2 = 0.f;
        for (int i = r0 - P; i <= r0 + P; i++) {
            float v = fp[refl(i)*W + j];
            s += v;
            s2 = fmaf(v, v, s2);
        }
        csA[c*512 + j] = s;
        csB[c*512 + j] = s2;
    }

    const int sc = wid & 7, sq = wid >> 3;
    float* src = (sq ? csB : csA) + sc*512;
    float* pr  = pref + wid*513;

    for (int r = r0; r < r0 + ROWS; r++) {
        __syncthreads();   // csA/B for row r ready; prev pref consumers done

        // warp-owned full-width scan
        {
            float seg[16];
            float run = 0.f;
            int base = lane * 16;
#pragma unroll
            for (int i = 0; i < 16; i++) { run += src[base + i]; seg[i] = run; }
            float v = run;
#pragma unroll
            for (int d = 1; d < 32; d <<= 1) {
                float t = __shfl_up_sync(0xffffffffu, v, d);
                if (lane >= d) v += t;
            }
            float carry = v - run;
#pragma unroll
            for (int i = 0; i < 16; i++) pr[base + 1 + i] = seg[i] + carry;
            if (lane == 0) pr[0] = 0.f;
        }
        __syncthreads();

        // prefetch next row's column updates (latency hidden by window math)
        float nva[8], nvs[8];
        const bool more = (r + 1 < r0 + ROWS);
        if (more) {
            int ra = refl(r + 1 + P), rs = refl(r - P);
#pragma unroll
            for (int c = 0; c < 8; c++) {
                const float* fp = g_f + ((size_t)(b*8 + c)) * PLANE;
                nva[c] = fp[ra*W + j];
                nvs[c] = fp[rs*W + j];
            }
        }

        const int lo = j - P, hi = j + P;
        const int loC = max(lo, 0), hiC = min(hi, W - 1);
        float rowacc = 0.f;
#pragma unroll
        for (int c = 0; c < 8; c++) {
            const float* pA = pref + c*513;
            const float* pB = pref + (8 + c)*513;
            float Sx = pA[hiC + 1] - pA[loC];
            float Sy = pB[hiC + 1] - pB[loC];
            if (lo < 0) {
                Sx += pA[-lo + 1] - pA[1];
                Sy += pB[-lo + 1] - pB[1];
            }
            if (hi > W - 1) {
                Sx += pA[W - 1] - pA[2*(W - 1) - hi];
                Sy += pB[W - 1] - pB[2*(W - 1) - hi];
            }
            float m  = Sx * inv;
            float m2 = Sy * inv;
            rowacc += sqrtf(fmaxf(m2 - m*m, 1e-6f));
        }
        g_maps[(size_t)scale*NPIX + ((size_t)b*H + r)*W + j] =
            powf(rowacc * 0.125f, 0.8f);

        if (more) {
#pragma unroll
            for (int c = 0; c < 8; c++) {
                csA[c*512 + j] += nva[c] - nvs[c];
                csB[c*512 + j] += nva[c]*nva[c] - nvs[c]*nvs[c];
            }
        }
    }
}

// ---------------------------------------------------------------------------
// Fusion + level-1 histogram
// ---------------------------------------------------------------------------
__global__ void fuse_hist1_k(const float* __restrict__ fw, const float* __restrict__ fb) {
    __shared__ unsigned h[8192];
    for (int i = threadIdx.x; i < 8192; i += blockDim.x) h[i] = 0u;
    __syncthreads();
    const float w0 = fw[0], w1 = fw[1], w2 = fw[2], b0 = fb[0];
    const size_t N = NPIX;
    for (size_t i = (size_t)blockIdx.x*blockDim.x + threadIdx.x; i < N;
         i += (size_t)gridDim.x*blockDim.x) {
        float v = w0*g_maps[i] + w1*g_maps[i + N] + w2*g_maps[i + 2*N] + b0;
        v = fmaxf(v, 0.f);
        g_fused[i] = v;
        atomicAdd(&h[__float_as_uint(v) >> 19], 1u);
    }
    __syncthreads();
    for (int i = threadIdx.x; i < 8192; i += blockDim.x)
        if (h[i]) atomicAdd(&g_h1[i], h[i]);
}

__device__ void findRank(const unsigned* __restrict__ hist, int nbins, unsigned rank,
                         unsigned* sbin, unsigned* srem,
                         unsigned* sp, unsigned* sb) {
    __syncthreads();
    const int tid = threadIdx.x;
    const int chunk = nbins / 256;
    unsigned loc = 0;
    for (int i = 0; i < chunk; i++) loc += hist[tid*chunk + i];
    sp[tid] = loc;
    __syncthreads();
    if (tid == 0) {
        unsigned c = 0;
        for (int i = 0; i < 256; i++) { sb[i] = c; c += sp[i]; }
    }
    __syncthreads();
    unsigned cum = sb[tid];
    for (int i = 0; i < chunk; i++) {
        unsigned cnt = hist[tid*chunk + i];
        if (rank >= cum && rank < cum + cnt) { *sbin = tid*chunk + i; *srem = rank - cum; }
        cum += cnt;
    }
    __syncthreads();
}

__global__ void scan1_k() {
    __shared__ unsigned sp[256], sb[256];
    __shared__ unsigned rbin, rrem;
    const unsigned ranks[4] = {524287u, 524288u, 1572863u, 1572864u};
    for (int r = 0; r < 4; r++) {
        findRank(g_h1, 8192, ranks[r], &rbin, &rrem, sp, sb);
        if (threadIdx.x == 0) { g_qs.pref1[r] = rbin; g_qs.rem[r] = rrem; }
        __syncthreads();
    }
}

__global__ void hist2_k() {
    extern __shared__ unsigned h2s[];   // 4*8192
    for (int i = threadIdx.x; i < 4*8192; i += blockDim.x) h2s[i] = 0u;
    __syncthreads();
    unsigned p0 = g_qs.pref1[0], p1 = g_qs.pref1[1];
    unsigned p2 = g_qs.pref1[2], p3 = g_qs.pref1[3];
    const uint4* fp = (const uint4*)g_fused;
    const size_t N4 = NPIX/4;
    for (size_t i = (size_t)blockIdx.x*blockDim.x + threadIdx.x; i < N4;
         i += (size_t)gridDim.x*blockDim.x) {
        uint4 v = fp[i];
        uint32_t bb[4] = {v.x, v.y, v.z, v.w};
#pragma unroll
        for (int e = 0; e < 4; e++) {
            unsigned hi = bb[e] >> 19, mid = (bb[e] >> 6) & 8191u;
            if (hi == p0) atomicAdd(&h2s[mid], 1u);
            if (hi == p1) atomicAdd(&h2s[8192 + mid], 1u);
            if (hi == p2) atomicAdd(&h2s[16384 + mid], 1u);
            if (hi == p3) atomicAdd(&h2s[24576 + mid], 1u);
        }
    }
    __syncthreads();
    for (int i = threadIdx.x; i < 4*8192; i += blockDim.x)
        if (h2s[i]) atomicAdd(&g_h2[i], h2s[i]);
}

__global__ void scan2_k() {
    __shared__ unsigned sp[256], sb[256];
    __shared__ unsigned rbin, rrem;
    for (int r = 0; r < 4; r++) {
        unsigned rank = g_qs.rem[r];
        findRank(g_h2 + r*8192, 8192, rank, &rbin, &rrem, sp, sb);
        if (threadIdx.x == 0) {
            g_qs.pref2[r] = (g_qs.pref1[r] << 13) | rbin;
            g_qs.rem[r]   = rrem;
        }
        __syncthreads();
    }
}

__global__ void hist3_k() {
    __shared__ unsigned h[4*64];
    for (int i = threadIdx.x; i < 4*64; i += blockDim.x) h[i] = 0u;
    __syncthreads();
    unsigned p0 = g_qs.pref2[0], p1 = g_qs.pref2[1];
    unsigned p2 = g_qs.pref2[2], p3 = g_qs.pref2[3];
    const uint4* fp = (const uint4*)g_fused;
    const size_t N4 = NPIX/4;
    for (size_t i = (size_t)blockIdx.x*blockDim.x + threadIdx.x; i < N4;
         i += (size_t)gridDim.x*blockDim.x) {
        uint4 v = fp[i];
        uint32_t bb[4] = {v.x, v.y, v.z, v.w};
#pragma unroll
        for (int e = 0; e < 4; e++) {
            unsigned hi = bb[e] >> 6, lo = bb[e] & 63u;
            if (hi == p0) atomicAdd(&h[lo], 1u);
            if (hi == p1) atomicAdd(&h[64 + lo], 1u);
            if (hi == p2) atomicAdd(&h[128 + lo], 1u);
            if (hi == p3) atomicAdd(&h[192 + lo], 1u);
        }
    }
    __syncthreads();
    for (int i = threadIdx.x; i < 4*64; i += blockDim.x)
        if (h[i]) atomicAdd(&g_h3[i], h[i]);
}

__global__ void xstats_k(const float* __restrict__ x) {
    const int bc = blockIdx.x;
    const int sl = blockIdx.y;
    const float* p = x + ((size_t)bc << 18) + (size_t)sl * 32768;
    float s = 0.f, s2 = 0.f;
    for (int i = threadIdx.x; i < 32768; i += 256) {
        float v = p[i];
        s += v;
        s2 = fmaf(v, v, s2);
    }
#pragma unroll
    for (int o = 16; o; o >>= 1) {
        s  += __shfl_xor_sync(0xffffffffu, s, o);
        s2 += __shfl_xor_sync(0xffffffffu, s2, o);
    }
    __shared__ float ss[8], ss2[8];
    int w = threadIdx.x >> 5, l = threadIdx.x & 31;
    if (l == 0) { ss[w] = s; ss2[w] = s2; }
    __syncthreads();
    if (threadIdx.x == 0) {
        float a = 0.f, a2 = 0.f;
        for (int i = 0; i < 8; i++) { a += ss[i]; a2 += ss2[i]; }
        atomicAdd(&g_stats[bc].x, a);
        atomicAdd(&g_stats[bc].y, a2);
    }
}

// scan3 + thresholds fused (1 warp + a bit)
__global__ void scan3thr_k(const float* __restrict__ chw) {
    __shared__ float sv[4];
    const int t = threadIdx.x;
    if (t < 4) {
        unsigned rank = g_qs.rem[t];
        unsigned cum = 0, bin = 0;
        for (int i = 0; i < 64; i++) {
            unsigned c = g_h3[t*64 + i];
            if (rank >= cum && rank < cum + c) bin = (unsigned)i;
            cum += c;
        }
        sv[t] = __uint_as_float((g_qs.pref2[t] << 6) | bin);
    }
    __syncthreads();
    float q25 = sv[0] + 0.75f*(sv[1] - sv[0]);
    float q75 = sv[2] + 0.25f*(sv[3] - sv[2]);
    float iqr = q75 - q25;
    if (iqr < 1e-5f) iqr = 0.05f;

    const int c = t & 3;
    float w0 = chw[0], w1 = chw[1], w2 = chw[2], w3 = chw[3];
    float mx = fmaxf(fmaxf(w0, w1), fmaxf(w2, w3));
    float e0 = expf(w0 - mx), e1 = expf(w1 - mx), e2 = expf(w2 - mx), e3 = expf(w3 - mx);
    float se = e0 + e1 + e2 + e3;
    float cw = ((c == 0) ? e0 : (c == 1) ? e1 : (c == 2) ? e2 : e3) / se;

    float2 st = g_stats[t];
    const float N = (float)PLANE;
    float var = (st.y - st.x*st.x/N) / (N - 1.f);
    float gstd = sqrtf(fmaxf(var, 0.f));

    float lower = q25 - 0.5f*iqr;
    float upper = q75 + 0.5f*iqr;
    float gf = fminf(fmaxf(gstd*5.f, 0.5f), 2.f);
    lower *= gf; upper *= gf;
    float cf = fminf(fmaxf(cw*gstd*2.f, 0.8f), 1.2f);
    lower *= cf; upper *= cf;

    float d = fabsf(upper - lower);
#pragma unroll
    for (int o = 16; o; o >>= 1) d = fminf(d, __shfl_xor_sync(0xffffffffu, d, o));
    if (d < 1e-5f) {
        float mt = 0.5f*(upper + lower);
        lower = mt - 0.05f;
        upper = mt + 0.05f;
    }
    g_thr[t]      = lower;
    g_thr[32 + t] = fmaxf(upper - lower, 1e-5f);
}

__global__ void mask_k(float* __restrict__ out) {
    for (size_t i = (size_t)blockIdx.x*blockDim.x + threadIdx.x; i < (size_t)NPIX;
         i += (size_t)gridDim.x*blockDim.x) {
        int b = (int)(i >> 18);
        float v = g_fused[i];
        float acc = 0.f;
#pragma unroll
        for (int c = 0; c < 4; c++) {
            float lo  = g_thr[b*4 + c];
            float dif = g_thr[32 + b*4 + c];
            float nrm = fminf(fmaxf((v - lo)/dif, 0.f), 1.f);
            acc += 1.f/(1.f + expf(3.f - 6.f*nrm));
        }
        out[i] = 0.25f*acc;
    }
}

// ---------------------------------------------------------------------------
// Launch
// ---------------------------------------------------------------------------
extern "C" void kernel_launch(void* const* d_in, const int* in_sizes, int n_in,
                              void* d_out, int out_size) {
    const float* x        = (const float*)d_in[0];
    const float* conv1_w  = (const float*)d_in[1];
    const float* conv1_b  = (const float*)d_in[2];
    const float* conv2_w  = (const float*)d_in[3];
    const float* conv2_b  = (const float*)d_in[4];
    const float* conv3_w  = (const float*)d_in[5];
    const float* conv3_b  = (const float*)d_in[6];
    const float* fusion_w = (const float*)d_in[7];
    const float* fusion_b = (const float*)d_in[8];
    const float* chw      = (const float*)d_in[9];
    float* out = (float*)d_out;

    uint2* f1p; cudaGetSymbolAddress((void**)&f1p, g_f1p);
    uint2* f2p; cudaGetSymbolAddress((void**)&f2p, g_f2p);
    float* f  ; cudaGetSymbolAddress((void**)&f  , g_f);
    uint4 *w2b, *w2s, *w3b, *w3s;
    cudaGetSymbolAddress((void**)&w2b, g_w2b);
    cudaGetSymbolAddress((void**)&w2s, g_w2s);
    cudaGetSymbolAddress((void**)&w3b, g_w3b);
    cudaGetSymbolAddress((void**)&w3s, g_w3s);

    const int smemP  = 1188 * 8 * 8;                 // 76032
    const int smemBX = (4096 + 4096 + 16*513) * 4;   // 65668
    const int smemH2 = 4 * 8192 * 4;                 // 131072
    cudaFuncSetAttribute(convP_k<2, 16, true, true>,  cudaFuncAttributeMaxDynamicSharedMemorySize, smemP);
    cudaFuncSetAttribute(convP_k<1, 8, false, false>, cudaFuncAttributeMaxDynamicSharedMemorySize, smemP);
    cudaFuncSetAttribute(boxstd_k, cudaFuncAttributeMaxDynamicSharedMemorySize, smemBX);
    cudaFuncSetAttribute(hist2_k,  cudaFuncAttributeMaxDynamicSharedMemorySize, smemH2);

    prep_k<<<32, 256>>>(conv1_w, conv2_w, conv3_w);
    xstats_k<<<dim3(32, 8), 256>>>(x);

    conv1_k<<<dim3(W/64, H/8, B), 256>>>(x, conv1_b);
    convP_k<2, 16, true, true><<<dim3(W/64, H/16, B), 256, smemP>>>(f1p, w2b, w2s, conv2_b, f2p, 0);
    convP_k<1, 8, false, false><<<dim3(W/64, H/16, B), 256, smemP>>>(f2p, w3b, w3s, conv3_b, 0, f);

    boxstd_k<<<dim3(H/64, 3, B), 512, smemBX>>>();

    fuse_hist1_k<<<448, 256>>>(fusion_w, fusion_b);
    scan1_k<<<1, 256>>>();
    hist2_k<<<148, 512, smemH2>>>();
    scan2_k<<<1, 256>>>();
    hist3_k<<<256, 256>>>();
    scan3thr_k<<<1, 32>>>(chw);

    mask_k<<<1024, 256>>>(out);
}

// round 16
// speedup vs baseline: 1.1201x; 1.0174x over previous
#include <cuda_runtime.h>
#include <cuda_bf16.h>
#include <math.h>
#include <stdint.h>

#define B  8
#define H  512
#define W  512
#define PLANE (H*W)
#define NPIX (B*PLANE)

// ---------------------------------------------------------------------------
// Scratch
// ---------------------------------------------------------------------------
__device__ __align__(16) uint2 g_f1p[(size_t)B*16*PLANE]; // packed split pairs (c, c+8)
__device__ __align__(16) uint2 g_f2p[(size_t)B* 8*PLANE];
__device__ float g_f [(size_t)B*8*PLANE];
__device__ float g_maps[(size_t)3*NPIX];
__device__ float g_fused[(size_t)NPIX];
__device__ unsigned g_h1[8192];
__device__ unsigned g_h2[4*8192];
__device__ unsigned g_h3[4*64];
__device__ float2 g_stats[32];
__device__ float g_thr[64];

__device__ uint32_t g_w1b[9*4*32], g_w1s[9*4*32];          // [s][k4][co32]
__device__ __align__(16) uint32_t g_w2b[2*9*4*8*4], g_w2s[2*9*4*8*4];
__device__ __align__(16) uint32_t g_w3b[9*4*8*4],   g_w3s[9*4*8*4];

struct QState {
    unsigned pref1[4];
    unsigned rem[4];
    unsigned pref2[4];
    float q25, q75, iqr;
};
__device__ QState g_qs;

// ---------------------------------------------------------------------------
__device__ __forceinline__ uint32_t f2tf(float f) {
    uint32_t r;
    asm("cvt.rna.tf32.f32 %0, %1;" : "=r"(r) : "f"(f));
    return r;
}
__device__ __forceinline__ void tf_split(float v, uint32_t& vb, uint32_t& vs) {
    vb = f2tf(v);
    vs = f2tf(v - __uint_as_float(vb));
}
__device__ __forceinline__ uint32_t bpack2(float v0, float v1, uint32_t& smw) {
    __nv_bfloat16 b0 = __float2bfloat16(v0), b1 = __float2bfloat16(v1);
    float r0 = v0 - __bfloat162float(b0);
    float r1 = v1 - __bfloat162float(b1);
    __nv_bfloat16 s0 = __float2bfloat16(r0), s1 = __float2bfloat16(r1);
    smw = (uint32_t)__bfloat16_as_ushort(s0) | ((uint32_t)__bfloat16_as_ushort(s1) << 16);
    return (uint32_t)__bfloat16_as_ushort(b0) | ((uint32_t)__bfloat16_as_ushort(b1) << 16);
}
__device__ __forceinline__ void mma16(float* d, const uint32_t* a, uint32_t b0, uint32_t b1) {
    asm("mma.sync.aligned.m16n8k16.row.col.f32.bf16.bf16.f32 "
        "{%0,%1,%2,%3}, {%4,%5,%6,%7}, {%8,%9}, {%0,%1,%2,%3};"
        : "+f"(d[0]), "+f"(d[1]), "+f"(d[2]), "+f"(d[3])
        : "r"(a[0]), "r"(a[1]), "r"(a[2]), "r"(a[3]), "r"(b0), "r"(b1));
}
__device__ __forceinline__ void mma4(float* d, uint32_t a0, uint32_t a1, uint32_t b0) {
    asm("mma.sync.aligned.m16n8k4.row.col.f32.tf32.tf32.f32 "
        "{%0,%1,%2,%3}, {%4,%5}, {%6}, {%0,%1,%2,%3};"
        : "+f"(d[0]), "+f"(d[1]), "+f"(d[2]), "+f"(d[3])
        : "r"(a0), "r"(a1), "r"(b0));
}
__device__ __forceinline__ float lrelu(float v) { return v >= 0.f ? v : 0.2f * v; }

__device__ __forceinline__ void cpasync8(uint32_t saddr, const void* gptr, bool ok) {
    int sz = ok ? 8 : 0;
    asm volatile("cp.async.ca.shared.global [%0], [%1], 8, %2;\n"
                 :: "r"(saddr), "l"(gptr), "r"(sz));
}

// ---------------------------------------------------------------------------
// Weight prep + accumulator zeroing (fused)
// ---------------------------------------------------------------------------
__global__ void prep_k(const float* __restrict__ w1, const float* __restrict__ w2,
                       const float* __restrict__ w3) {
    int i0 = blockIdx.x * blockDim.x + threadIdx.x;
    int n = gridDim.x * blockDim.x;
    for (int j = i0; j < 8192; j += n)    g_h1[j] = 0u;
    for (int j = i0; j < 4*8192; j += n)  g_h2[j] = 0u;
    for (int j = i0; j < 4*64; j += n)    g_h3[j] = 0u;
    for (int j = i0; j < 32; j += n)      g_stats[j] = make_float2(0.f, 0.f);

    for (int j = i0; j < 9*4*32; j += n) {
        int s = j / 128, k = (j >> 5) & 3, co = j & 31;
        tf_split(w1[co*36 + k*9 + s], g_w1b[j], g_w1s[j]);
    }
    for (int j = i0; j < 2*9*4*8*4; j += n) {
        int reg = j & 3, nq = (j >> 2) & 7, tt = (j >> 5) & 3;
        int s = (j >> 7) % 9, chunk = j / 1152;
        int co = nq + 8*(reg & 1);
        int pu = tt + 4*(reg >> 1);
        float v0 = w2[co*288 + (chunk*16 + pu)*9 + s];
        float v1 = w2[co*288 + (chunk*16 + pu + 8)*9 + s];
        uint32_t smw;
        uint32_t bg = bpack2(v0, v1, smw);
        g_w2b[j] = bg; g_w2s[j] = smw;
    }
    for (int j = i0; j < 9*4*8*4; j += n) {
        int reg = j & 3, nq = (j >> 2) & 7, tt = (j >> 5) & 3;
        int s = (j >> 7) % 9;
        int co = nq + 8*(reg & 1);
        int pu = tt + 4*(reg >> 1);
        float v0 = 0.f, v1 = 0.f;
        if (co < 8) {
            v0 = w3[co*144 + pu*9 + s];
            v1 = w3[co*144 + (pu + 8)*9 + s];
        }
        uint32_t smw;
        uint32_t bg = bpack2(v0, v1, smw);
        g_w3b[j] = bg; g_w3s[j] = smw;
    }
}

// ---------------------------------------------------------------------------
// conv1: 4 -> 32, leaky. Block 8 rows x 64 cols, 2 CTAs/SM.
// ---------------------------------------------------------------------------
__global__ __launch_bounds__(256, 2)
void conv1_k(const float* __restrict__ in, const float* __restrict__ bias) {
    __shared__ uint2 t1[4*684];
    const int tid = threadIdx.x;
    const int wid = tid >> 5, lane = tid & 31;
    const int nq = lane >> 2, tt = lane & 3;
    const int x0 = blockIdx.x * 64, y0 = blockIdx.y * 8, b = blockIdx.z;

    for (int i = tid; i < 4*10*66; i += 256) {
        int c = i / 660, rem = i % 660;
        int yy = rem / 66, xx = rem % 66;
        int gy = y0 + yy - 1, gx = x0 + xx - 1;
        float v = 0.f;
        if (gy >= 0 && gy < H && gx >= 0 && gx < W)
            v = in[(((size_t)b*4 + c)*H + gy)*W + gx];
        uint32_t vb, vs;
        tf_split(v, vb, vs);
        t1[c*684 + yy*68 + xx] = make_uint2(vb, vs);
    }
    __syncthreads();

    float acc[2][8][4];
#pragma unroll
    for (int m = 0; m < 2; m++)
#pragma unroll
        for (int g = 0; g < 8; g++)
#pragma unroll
            for (int q = 0; q < 4; q++) acc[m][g][q] = 0.f;

#pragma unroll
    for (int s = 0; s < 9; s++) {
        const int kh = s / 3, kw = s % 3;
        int wb = (s*4 + tt)*32;
        uint32_t a0b = g_w1b[wb + nq],      a1b = g_w1b[wb + nq + 8];
        uint32_t a2b = g_w1b[wb + 16 + nq], a3b = g_w1b[wb + 24 + nq];
        uint32_t a0s = g_w1s[wb + nq],      a1s = g_w1s[wb + nq + 8];
        uint32_t a2s = g_w1s[wb + 16 + nq], a3s = g_w1s[wb + 24 + nq];
        int base = tt*684 + (wid + kh)*68 + nq + kw;
#pragma unroll
        for (int g = 0; g < 8; g++) {
            uint2 bv = t1[base + g*8];
            mma4(acc[0][g], a0b, a1b, bv.x);
            mma4(acc[0][g], a0s, a1s, bv.x);
            mma4(acc[0][g], a0b, a1b, bv.y);
            mma4(acc[1][g], a2b, a3b, bv.x);
            mma4(acc[1][g], a2s, a3s, bv.x);
            mma4(acc[1][g], a2b, a3b, bv.y);
        }
    }

    const int gy = y0 + wid;
#pragma unroll
    for (int m = 0; m < 2; m++) {
        int co0 = m*16 + nq;
        float b0 = bias[co0], b8 = bias[co0 + 8];
        size_t plane = (size_t)(b*16 + m*8 + nq);
#pragma unroll
        for (int g = 0; g < 8; g++) {
            int pe = x0 + g*8 + 2*tt;
            float v0 = lrelu(acc[m][g][0] + b0);
            float v1 = lrelu(acc[m][g][1] + b0);
            float v2 = lrelu(acc[m][g][2] + b8);
            float v3 = lrelu(acc[m][g][3] + b8);
            uint32_t se, so;
            uint32_t be = bpack2(v0, v2, se);
            uint32_t bo = bpack2(v1, v3, so);
            *(uint4*)&g_f1p[plane*PLANE + (size_t)gy*W + pe] = make_uint4(be, se, bo, so);
        }
    }
}

// ---------------------------------------------------------------------------
// conv2/conv3: bf16 m16n8k16, warp-per-row cp.async staging (rr invariant
// under pix+=32), incremental swizzled mainloop addressing.
// ---------------------------------------------------------------------------
template<int CHUNKS, int COUT, bool LEAKY, bool PACKOUT>
__global__ __launch_bounds__(256, 2)
void convP_k(const uint2* __restrict__ inp, const uint4* __restrict__ wb4,
             const uint4* __restrict__ ws4, const float* __restrict__ bias,
             uint2* __restrict__ outp, float* __restrict__ outf) {
    extern __shared__ uint2 tile[];   // [1188*8]
    const int tid = threadIdx.x;
    const int wid = tid >> 5, lane = tid & 31;
    const int nq = lane >> 2, tt = lane & 3;
    const int x0 = blockIdx.x * 64, y0 = blockIdx.y * 16, b = blockIdx.z;
    const uint32_t smem_base = (uint32_t)__cvta_generic_to_shared(tile);

    float acc[16][4];
#pragma unroll
    for (int g = 0; g < 16; g++)
#pragma unroll
        for (int q = 0; q < 4; q++) acc[g][q] = 0.f;

#pragma unroll 1
    for (int chunk = 0; chunk < CHUNKS; chunk++) {
        __syncthreads();
        {
            const uint2* gplane = inp + (((size_t)b*CHUNKS + chunk)*8)*PLANE;
#pragma unroll 1
            for (int yy = wid; yy < 18; yy += 8) {
                int gy = y0 + yy - 1;
                bool rowok = (gy >= 0) && (gy < H);
                int gyc = rowok ? gy : 0;
                int pix0 = yy*66 + lane;
                int rr = (pix0 + (pix0 >> 2)) & 3;
                bool ok0, ok1, ok2;
                {
                    int gx = x0 + lane - 1;
                    ok0 = rowok && (gx >= 0) && (gx < W);
                    ok1 = rowok && (lane < 34) && (gx + 32 < W);
                    ok2 = rowok && (lane < 2);
                }
                const uint2* grow = gplane + (size_t)gyc*W + (x0 - 1 + lane);
                uint32_t sbase = smem_base + (uint32_t)(pix0*8)*8u;
#pragma unroll
                for (int u = 0; u < 8; u++) {
                    int pos = 2*(((u & 3) + rr) & 3) + (u >> 2);
                    const uint2* gu = grow + (size_t)u*PLANE;
                    uint32_t su = sbase + (uint32_t)pos*8u;
                    cpasync8(su, ok0 ? gu : (const void*)inp, ok0);
                    if (lane < 34)
                        cpasync8(su + 2048u, ok1 ? (gu + 32) : (const void*)inp, ok1);
                    if (lane < 2)
                        cpasync8(su + 4096u, ok2 ? (gu + 64) : (const void*)inp, ok2);
                }
            }
        }
        asm volatile("cp.async.commit_group;\n");
        asm volatile("cp.async.wait_group 0;\n");
        __syncthreads();

#pragma unroll
        for (int s = 0; s < 9; s++) {
            const int kh = s / 3, kw = s % 3;
            uint4 A = wb4[((chunk*9 + s)*4 + tt)*8 + nq];
            uint4 S = ws4[((chunk*9 + s)*4 + tt)*8 + nq];
            uint32_t ab[4]  = {A.x, A.y, A.z, A.w};
            uint32_t as_[4] = {S.x, S.y, S.z, S.w};

            int pix0 = (2*wid + kh)*66 + nq + kw;
            int rr0 = (pix0 + (pix0 >> 2)) & 3;
            int t0 = pix0*8 + 2*((tt + rr0) & 3);
            int pix1 = pix0 + 66;
            int rr1 = (pix1 + (pix1 >> 2)) & 3;
            int t1 = pix1*8 + 2*((tt + rr1) & 3);
#pragma unroll
            for (int gg = 0; gg < 8; gg++) {
                uint4 Bv0 = *(const uint4*)&tile[t0];
                mma16(acc[gg], ab,  Bv0.x, Bv0.z);
                mma16(acc[gg], as_, Bv0.x, Bv0.z);
                mma16(acc[gg], ab,  Bv0.y, Bv0.w);
                uint4 Bv1 = *(const uint4*)&tile[t1];
                mma16(acc[8+gg], ab,  Bv1.x, Bv1.z);
                mma16(acc[8+gg], as_, Bv1.x, Bv1.z);
                mma16(acc[8+gg], ab,  Bv1.y, Bv1.w);
                t0 = (t0 + 64) ^ 4;
                t1 = (t1 + 64) ^ 4;
            }
        }
    }

    if (PACKOUT) {
        float b0 = bias[nq], b8 = bias[nq + 8];
        size_t plane = (size_t)(b*8 + nq);
#pragma unroll
        for (int g = 0; g < 16; g++) {
            int gy = y0 + 2*wid + (g >> 3);
            int pe = x0 + (g & 7)*8 + 2*tt;
            float v0 = acc[g][0] + b0, v1 = acc[g][1] + b0;
            float v2 = acc[g][2] + b8, v3 = acc[g][3] + b8;
            if (LEAKY) { v0 = lrelu(v0); v1 = lrelu(v1); v2 = lrelu(v2); v3 = lrelu(v3); }
            uint32_t se, so;
            uint32_t be = bpack2(v0, v2, se);
            uint32_t bo = bpack2(v1, v3, so);
            *(uint4*)&outp[plane*PLANE + (size_t)gy*W + pe] = make_uint4(be, se, bo, so);
        }
    } else {
        float b0 = bias[nq];
#pragma unroll
        for (int g = 0; g < 16; g++) {
            int gy = y0 + 2*wid + (g >> 3);
            int pe = x0 + (g & 7)*8 + 2*tt;
            float2 o0;
            o0.x = acc[g][0] + b0; o0.y = acc[g][1] + b0;
            if (LEAKY) { o0.x = lrelu(o0.x); o0.y = lrelu(o0.y); }
            *(float2*)&outf[(((size_t)b*COUT + nq)*H + gy)*W + pe] = o0;
        }
    }
}

// ---------------------------------------------------------------------------
// Multi-scale box std maps — prefetch hoisted above the scan
// ---------------------------------------------------------------------------
__device__ __forceinline__ int refl(int i) {
    return i < 0 ? -i : (i > H - 1 ? 2*(H - 1) - i : i);
}

__global__ __launch_bounds__(512)
void boxstd_k() {
    constexpr int ROWS = 64;
    extern __shared__ float bsm[];
    float* csA  = bsm;
    float* csB  = bsm + 4096;
    float* pref = bsm + 8192;

    const int j    = threadIdx.x;
    const int lane = j & 31;
    const int wid  = j >> 5;
    const int strip = blockIdx.x;
    const int scale = blockIdx.y;
    const int b     = blockIdx.z;

    const int K = (scale == 0) ? 11 : (scale == 1) ? 25 : 49;
    const int P = K >> 1;
    const float inv = 1.f / (float)(K * K);
    const int r0 = strip * ROWS;

    for (int c = 0; c < 8; c++) {
        const float* fp = g_f + ((size_t)(b*8 + c)) * PLANE;
        float s = 0.f, s2 = 0.f;
        for (int i = r0 - P; i <= r0 + P; i++) {
            float v = fp[refl(i)*W + j];
            s += v;
            s2 = fmaf(v, v, s2);
        }
        csA[c*512 + j] = s;
        csB[c*512 + j] = s2;
    }

    const int sc = wid & 7, sq = wid >> 3;
    float* src = (sq ? csB : csA) + sc*512;
    float* pr  = pref + wid*513;

    for (int r = r0; r < r0 + ROWS; r++) {
        __syncthreads();   // csA/B for row r ready; prev pref consumers done

        // prefetch next row's column updates FIRST (hidden behind scan + window math)
        float nva[8], nvs[8];
        const bool more = (r + 1 < r0 + ROWS);
        if (more) {
            int ra = refl(r + 1 + P), rs = refl(r - P);
#pragma unroll
            for (int c = 0; c < 8; c++) {
                const float* fp = g_f + ((size_t)(b*8 + c)) * PLANE;
                nva[c] = fp[ra*W + j];
                nvs[c] = fp[rs*W + j];
            }
        }

        // warp-owned full-width scan
        {
            float seg[16];
            float run = 0.f;
            int base = lane * 16;
#pragma unroll
            for (int i = 0; i < 16; i++) { run += src[base + i]; seg[i] = run; }
            float v = run;
#pragma unroll
            for (int d = 1; d < 32; d <<= 1) {
                float t = __shfl_up_sync(0xffffffffu, v, d);
                if (lane >= d) v += t;
            }
            float carry = v - run;
#pragma unroll
            for (int i = 0; i < 16; i++) pr[base + 1 + i] = seg[i] + carry;
            if (lane == 0) pr[0] = 0.f;
        }
        __syncthreads();

        const int lo = j - P, hi = j + P;
        const int loC = max(lo, 0), hiC = min(hi, W - 1);
        float rowacc = 0.f;
#pragma unroll
        for (int c = 0; c < 8; c++) {
            const float* pA = pref + c*513;
            const float* pB = pref + (8 + c)*513;
            float Sx = pA[hiC + 1] - pA[loC];
            float Sy = pB[hiC + 1] - pB[loC];
            if (lo < 0) {
                Sx += pA[-lo + 1] - pA[1];
                Sy += pB[-lo + 1] - pB[1];
            }
            if (hi > W - 1) {
                Sx += pA[W - 1] - pA[2*(W - 1) - hi];
                Sy += pB[W - 1] - pB[2*(W - 1) - hi];
            }
            float m  = Sx * inv;
            float m2 = Sy * inv;
            rowacc += sqrtf(fmaxf(m2 - m*m, 1e-6f));
        }
        g_maps[(size_t)scale*NPIX + ((size_t)b*H + r)*W + j] =
            powf(rowacc * 0.125f, 0.8f);

        if (more) {
#pragma unroll
            for (int c = 0; c < 8; c++) {
                csA[c*512 + j] += nva[c] - nvs[c];
                csB[c*512 + j] += nva[c]*nva[c] - nvs[c]*nvs[c];
            }
        }
    }
}

// ---------------------------------------------------------------------------
// Fusion + level-1 histogram
// ---------------------------------------------------------------------------
__global__ void fuse_hist1_k(const float* __restrict__ fw, const float* __restrict__ fb) {
    __shared__ unsigned h[8192];
    for (int i = threadIdx.x; i < 8192; i += blockDim.x) h[i] = 0u;
    __syncthreads();
    const float w0 = fw[0], w1 = fw[1], w2 = fw[2], b0 = fb[0];
    const size_t N = NPIX;
    for (size_t i = (size_t)blockIdx.x*blockDim.x + threadIdx.x; i < N;
         i += (size_t)gridDim.x*blockDim.x) {
        float v = w0*g_maps[i] + w1*g_maps[i + N] + w2*g_maps[i + 2*N] + b0;
        v = fmaxf(v, 0.f);
        g_fused[i] = v;
        atomicAdd(&h[__float_as_uint(v) >> 19], 1u);
    }
    __syncthreads();
    for (int i = threadIdx.x; i < 8192; i += blockDim.x)
        if (h[i]) atomicAdd(&g_h1[i], h[i]);
}

__device__ void findRank(const unsigned* __restrict__ hist, int nbins, unsigned rank,
                         unsigned* sbin, unsigned* srem,
                         unsigned* sp, unsigned* sb) {
    __syncthreads();
    const int tid = threadIdx.x;
    const int chunk = nbins / 256;
    unsigned loc = 0;
    for (int i = 0; i < chunk; i++) loc += hist[tid*chunk + i];
    sp[tid] = loc;
    __syncthreads();
    if (tid == 0) {
        unsigned c = 0;
        for (int i = 0; i < 256; i++) { sb[i] = c; c += sp[i]; }
    }
    __syncthreads();
    unsigned cum = sb[tid];
    for (int i = 0; i < chunk; i++) {
        unsigned cnt = hist[tid*chunk + i];
        if (rank >= cum && rank < cum + cnt) { *sbin = tid*chunk + i; *srem = rank - cum; }
        cum += cnt;
    }
    __syncthreads();
}

__global__ void scan1_k() {
    __shared__ unsigned sp[256], sb[256];
    __shared__ unsigned rbin, rrem;
    const unsigned ranks[4] = {524287u, 524288u, 1572863u, 1572864u};
    for (int r = 0; r < 4; r++) {
        findRank(g_h1, 8192, ranks[r], &rbin, &rrem, sp, sb);
        if (threadIdx.x == 0) { g_qs.pref1[r] = rbin; g_qs.rem[r] = rrem; }
        __syncthreads();
    }
}

__global__ void hist2_k() {
    extern __shared__ unsigned h2s[];   // 4*8192
    for (int i = threadIdx.x; i < 4*8192; i += blockDim.x) h2s[i] = 0u;
    __syncthreads();
    unsigned p0 = g_qs.pref1[0], p1 = g_qs.pref1[1];
    unsigned p2 = g_qs.pref1[2], p3 = g_qs.pref1[3];
    const uint4* fp = (const uint4*)g_fused;
    const size_t N4 = NPIX/4;
    for (size_t i = (size_t)blockIdx.x*blockDim.x + threadIdx.x; i < N4;
         i += (size_t)gridDim.x*blockDim.x) {
        uint4 v = fp[i];
        uint32_t bb[4] = {v.x, v.y, v.z, v.w};
#pragma unroll
        for (int e = 0; e < 4; e++) {
            unsigned hi = bb[e] >> 19, mid = (bb[e] >> 6) & 8191u;
            if (hi == p0) atomicAdd(&h2s[mid], 1u);
            if (hi == p1) atomicAdd(&h2s[8192 + mid], 1u);
            if (hi == p2) atomicAdd(&h2s[16384 + mid], 1u);
            if (hi == p3) atomicAdd(&h2s[24576 + mid], 1u);
        }
    }
    __syncthreads();
    for (int i = threadIdx.x; i < 4*8192; i += blockDim.x)
        if (h2s[i]) atomicAdd(&g_h2[i], h2s[i]);
}

__global__ void scan2_k() {
    __shared__ unsigned sp[256], sb[256];
    __shared__ unsigned rbin, rrem;
    for (int r = 0; r < 4; r++) {
        unsigned rank = g_qs.rem[r];
        findRank(g_h2 + r*8192, 8192, rank, &rbin, &rrem, sp, sb);
        if (threadIdx.x == 0) {
            g_qs.pref2[r] = (g_qs.pref1[r] << 13) | rbin;
            g_qs.rem[r]   = rrem;
        }
        __syncthreads();
    }
}

__global__ void hist3_k() {
    __shared__ unsigned h[4*64];
    for (int i = threadIdx.x; i < 4*64; i += blockDim.x) h[i] = 0u;
    __syncthreads();
    unsigned p0 = g_qs.pref2[0], p1 = g_qs.pref2[1];
    unsigned p2 = g_qs.pref2[2], p3 = g_qs.pref2[3];
    const uint4* fp = (const uint4*)g_fused;
    const size_t N4 = NPIX/4;
    for (size_t i = (size_t)blockIdx.x*blockDim.x + threadIdx.x; i < N4;
         i += (size_t)gridDim.x*blockDim.x) {
        uint4 v = fp[i];
        uint32_t bb[4] = {v.x, v.y, v.z, v.w};
#pragma unroll
        for (int e = 0; e < 4; e++) {
            unsigned hi = bb[e] >> 6, lo = bb[e] & 63u;
            if (hi == p0) atomicAdd(&h[lo], 1u);
            if (hi == p1) atomicAdd(&h[64 + lo], 1u);
            if (hi == p2) atomicAdd(&h[128 + lo], 1u);
            if (hi == p3) atomicAdd(&h[192 + lo], 1u);
        }
    }
    __syncthreads();
    for (int i = threadIdx.x; i < 4*64; i += blockDim.x)
        if (h[i]) atomicAdd(&g_h3[i], h[i]);
}

__global__ void xstats_k(const float* __restrict__ x) {
    const int bc = blockIdx.x;
    const int sl = blockIdx.y;
    const float* p = x + ((size_t)bc << 18) + (size_t)sl * 32768;
    float s = 0.f, s2 = 0.f;
    for (int i = threadIdx.x; i < 32768; i += 256) {
        float v = p[i];
        s += v;
        s2 = fmaf(v, v, s2);
    }
#pragma unroll
    for (int o = 16; o; o >>= 1) {
        s  += __shfl_xor_sync(0xffffffffu, s, o);
        s2 += __shfl_xor_sync(0xffffffffu, s2, o);
    }
    __shared__ float ss[8], ss2[8];
    int w = threadIdx.x >> 5, l = threadIdx.x & 31;
    if (l == 0) { ss[w] = s; ss2[w] = s2; }
    __syncthreads();
    if (threadIdx.x == 0) {
        float a = 0.f, a2 = 0.f;
        for (int i = 0; i < 8; i++) { a += ss[i]; a2 += ss2[i]; }
        atomicAdd(&g_stats[bc].x, a);
        atomicAdd(&g_stats[bc].y, a2);
    }
}

// scan3 + thresholds fused (1 warp)
__global__ void scan3thr_k(const float* __restrict__ chw) {
    __shared__ float sv[4];
    const int t = threadIdx.x;
    if (t < 4) {
        unsigned rank = g_qs.rem[t];
        unsigned cum = 0, bin = 0;
        for (int i = 0; i < 64; i++) {
            unsigned c = g_h3[t*64 + i];
            if (rank >= cum && rank < cum + c) bin = (unsigned)i;
            cum += c;
        }
        sv[t] = __uint_as_float((g_qs.pref2[t] << 6) | bin);
    }
    __syncthreads();
    float q25 = sv[0] + 0.75f*(sv[1] - sv[0]);
    float q75 = sv[2] + 0.25f*(sv[3] - sv[2]);
    float iqr = q75 - q25;
    if (iqr < 1e-5f) iqr = 0.05f;

    const int c = t & 3;
    float w0 = chw[0], w1 = chw[1], w2 = chw[2], w3 = chw[3];
    float mx = fmaxf(fmaxf(w0, w1), fmaxf(w2, w3));
    float e0 = expf(w0 - mx), e1 = expf(w1 - mx), e2 = expf(w2 - mx), e3 = expf(w3 - mx);
    float se = e0 + e1 + e2 + e3;
    float cw = ((c == 0) ? e0 : (c == 1) ? e1 : (c == 2) ? e2 : e3) / se;

    float2 st = g_stats[t];
    const float N = (float)PLANE;
    float var = (st.y - st.x*st.x/N) / (N - 1.f);
    float gstd = sqrtf(fmaxf(var, 0.f));

    float lower = q25 - 0.5f*iqr;
    float upper = q75 + 0.5f*iqr;
    float gf = fminf(fmaxf(gstd*5.f, 0.5f), 2.f);
    lower *= gf; upper *= gf;
    float cf = fminf(fmaxf(cw*gstd*2.f, 0.8f), 1.2f);
    lower *= cf; upper *= cf;

    float d = fabsf(upper - lower);
#pragma unroll
    for (int o = 16; o; o >>= 1) d = fminf(d, __shfl_xor_sync(0xffffffffu, d, o));
    if (d < 1e-5f) {
        float mt = 0.5f*(upper + lower);
        lower = mt - 0.05f;
        upper = mt + 0.05f;
    }
    g_thr[t]      = lower;
    g_thr[32 + t] = fmaxf(upper - lower, 1e-5f);
}

__global__ void mask_k(float* __restrict__ out) {
    for (size_t i = (size_t)blockIdx.x*blockDim.x + threadIdx.x; i < (size_t)NPIX;
         i += (size_t)gridDim.x*blockDim.x) {
        int b = (int)(i >> 18);
        float v = g_fused[i];
        float acc = 0.f;
#pragma unroll
        for (int c = 0; c < 4; c++) {
            float lo  = g_thr[b*4 + c];
            float dif = g_thr[32 + b*4 + c];
            float nrm = fminf(fmaxf((v - lo)/dif, 0.f), 1.f);
            acc += 1.f/(1.f + expf(3.f - 6.f*nrm));
        }
        out[i] = 0.25f*acc;
    }
}

// ---------------------------------------------------------------------------
// Launch
// ---------------------------------------------------------------------------
extern "C" void kernel_launch(void* const* d_in, const int* in_sizes, int n_in,
                              void* d_out, int out_size) {
    const float* x        = (const float*)d_in[0];
    const float* conv1_w  = (const float*)d_in[1];
    const float* conv1_b  = (const float*)d_in[2];
    const float* conv2_w  = (const float*)d_in[3];
    const float* conv2_b  = (const float*)d_in[4];
    const float* conv3_w  = (const float*)d_in[5];
    const float* conv3_b  = (const float*)d_in[6];
    const float* fusion_w = (const float*)d_in[7];
    const float* fusion_b = (const float*)d_in[8];
    const float* chw      = (const float*)d_in[9];
    float* out = (float*)d_out;

    uint2* f1p; cudaGetSymbolAddress((void**)&f1p, g_f1p);
    uint2* f2p; cudaGetSymbolAddress((void**)&f2p, g_f2p);
    float* f  ; cudaGetSymbolAddress((void**)&f  , g_f);
    uint4 *w2b, *w2s, *w3b, *w3s;
    cudaGetSymbolAddress((void**)&w2b, g_w2b);
    cudaGetSymbolAddress((void**)&w2s, g_w2s);
    cudaGetSymbolAddress((void**)&w3b, g_w3b);
    cudaGetSymbolAddress((void**)&w3s, g_w3s);

    const int smemP  = 1188 * 8 * 8;                 // 76032
    const int smemBX = (4096 + 4096 + 16*513) * 4;   // 65668
    const int smemH2 = 4 * 8192 * 4;                 // 131072
    cudaFuncSetAttribute(convP_k<2, 16, true, true>,  cudaFuncAttributeMaxDynamicSharedMemorySize, smemP);
    cudaFuncSetAttribute(convP_k<1, 8, false, false>, cudaFuncAttributeMaxDynamicSharedMemorySize, smemP);
    cudaFuncSetAttribute(boxstd_k, cudaFuncAttributeMaxDynamicSharedMemorySize, smemBX);
    cudaFuncSetAttribute(hist2_k,  cudaFuncAttributeMaxDynamicSharedMemorySize, smemH2);

    prep_k<<<32, 256>>>(conv1_w, conv2_w, conv3_w);
    xstats_k<<<dim3(32, 8), 256>>>(x);

    conv1_k<<<dim3(W/64, H/8, B), 256>>>(x, conv1_b);
    convP_k<2, 16, true, true><<<dim3(W/64, H/16, B), 256, smemP>>>(f1p, w2b, w2s, conv2_b, f2p, 0);
    convP_k<1, 8, false, false><<<dim3(W/64, H/16, B), 256, smemP>>>(f2p, w3b, w3s, conv3_b, 0, f);

    boxstd_k<<<dim3(H/64, 3, B), 512, smemBX>>>();

    fuse_hist1_k<<<448, 256>>>(fusion_w, fusion_b);
    scan1_k<<<1, 256>>>();
    hist2_k<<<148, 512, smemH2>>>();
    scan2_k<<<1, 256>>>();
    hist3_k<<<256, 256>>>();
    scan3thr_k<<<1, 32>>>(chw);

    mask_k<<<1024, 256>>>(out);
}

// round 17
// speedup vs baseline: 1.1543x; 1.0306x over previous
#include <cuda_runtime.h>
#include <cuda_bf16.h>
#include <math.h>
#include <stdint.h>

#define B  8
#define H  512
#define W  512
#define PLANE (H*W)
#define NPIX (B*PLANE)

// ---------------------------------------------------------------------------
// Scratch
// ---------------------------------------------------------------------------
__device__ __align__(16) uint2 g_f1p[(size_t)B*16*PLANE]; // packed split pairs (c, c+8)
__device__ __align__(16) uint2 g_f2p[(size_t)B* 8*PLANE];
__device__ float g_f [(size_t)B*8*PLANE];
__device__ float g_maps[(size_t)3*NPIX];
__device__ float g_fused[(size_t)NPIX];
__device__ unsigned g_h1[8192];
__device__ unsigned g_h2[4*8192];
__device__ unsigned g_h3[4*64];
__device__ float2 g_stats[32];
__device__ float g_thr[64];

// conv1 tf32 split weights for m16n8k8: [step5][k8][co32], k = tap_local*4 + ci
__device__ uint32_t g_w1b[5*8*32], g_w1s[5*8*32];
__device__ __align__(16) uint32_t g_w2b[2*9*4*8*4], g_w2s[2*9*4*8*4];
__device__ __align__(16) uint32_t g_w3b[9*4*8*4],   g_w3s[9*4*8*4];

struct QState {
    unsigned pref1[4];
    unsigned rem[4];
    unsigned pref2[4];
    float q25, q75, iqr;
};
__device__ QState g_qs;

// ---------------------------------------------------------------------------
__device__ __forceinline__ uint32_t f2tf(float f) {
    uint32_t r;
    asm("cvt.rna.tf32.f32 %0, %1;" : "=r"(r) : "f"(f));
    return r;
}
__device__ __forceinline__ void tf_split(float v, uint32_t& vb, uint32_t& vs) {
    vb = f2tf(v);
    vs = f2tf(v - __uint_as_float(vb));
}
__device__ __forceinline__ uint32_t bpack2(float v0, float v1, uint32_t& smw) {
    __nv_bfloat16 b0 = __float2bfloat16(v0), b1 = __float2bfloat16(v1);
    float r0 = v0 - __bfloat162float(b0);
    float r1 = v1 - __bfloat162float(b1);
    __nv_bfloat16 s0 = __float2bfloat16(r0), s1 = __float2bfloat16(r1);
    smw = (uint32_t)__bfloat16_as_ushort(s0) | ((uint32_t)__bfloat16_as_ushort(s1) << 16);
    return (uint32_t)__bfloat16_as_ushort(b0) | ((uint32_t)__bfloat16_as_ushort(b1) << 16);
}
__device__ __forceinline__ void mma16(float* d, const uint32_t* a, uint32_t b0, uint32_t b1) {
    asm("mma.sync.aligned.m16n8k16.row.col.f32.bf16.bf16.f32 "
        "{%0,%1,%2,%3}, {%4,%5,%6,%7}, {%8,%9}, {%0,%1,%2,%3};"
        : "+f"(d[0]), "+f"(d[1]), "+f"(d[2]), "+f"(d[3])
        : "r"(a[0]), "r"(a[1]), "r"(a[2]), "r"(a[3]), "r"(b0), "r"(b1));
}
__device__ __forceinline__ void mma8(float* d, const uint32_t* a, uint32_t b0, uint32_t b1) {
    asm("mma.sync.aligned.m16n8k8.row.col.f32.tf32.tf32.f32 "
        "{%0,%1,%2,%3}, {%4,%5,%6,%7}, {%8,%9}, {%0,%1,%2,%3};"
        : "+f"(d[0]), "+f"(d[1]), "+f"(d[2]), "+f"(d[3])
        : "r"(a[0]), "r"(a[1]), "r"(a[2]), "r"(a[3]), "r"(b0), "r"(b1));
}
__device__ __forceinline__ float lrelu(float v) { return v >= 0.f ? v : 0.2f * v; }

__device__ __forceinline__ void cpasync8(uint32_t saddr, const void* gptr, bool ok) {
    int sz = ok ? 8 : 0;
    asm volatile("cp.async.ca.shared.global [%0], [%1], 8, %2;\n"
                 :: "r"(saddr), "l"(gptr), "r"(sz));
}

// ---------------------------------------------------------------------------
// Weight prep + accumulator zeroing (fused)
// ---------------------------------------------------------------------------
__global__ void prep_k(const float* __restrict__ w1, const float* __restrict__ w2,
                       const float* __restrict__ w3) {
    int i0 = blockIdx.x * blockDim.x + threadIdx.x;
    int n = gridDim.x * blockDim.x;
    for (int j = i0; j < 8192; j += n)    g_h1[j] = 0u;
    for (int j = i0; j < 4*8192; j += n)  g_h2[j] = 0u;
    for (int j = i0; j < 4*64; j += n)    g_h3[j] = 0u;
    for (int j = i0; j < 32; j += n)      g_stats[j] = make_float2(0.f, 0.f);

    // conv1 [step][k][co]: k = tap_local*4 + ci, tap = 2*step + tap_local
    for (int j = i0; j < 5*8*32; j += n) {
        int step = j >> 8, k = (j >> 5) & 7, co = j & 31;
        int tap = 2*step + (k >> 2);
        int ci = k & 3;
        float v = (tap <= 8) ? w1[co*36 + ci*9 + tap] : 0.f;
        tf_split(v, g_w1b[j], g_w1s[j]);
    }
    for (int j = i0; j < 2*9*4*8*4; j += n) {
        int reg = j & 3, nq = (j >> 2) & 7, tt = (j >> 5) & 3;
        int s = (j >> 7) % 9, chunk = j / 1152;
        int co = nq + 8*(reg & 1);
        int pu = tt + 4*(reg >> 1);
        float v0 = w2[co*288 + (chunk*16 + pu)*9 + s];
        float v1 = w2[co*288 + (chunk*16 + pu + 8)*9 + s];
        uint32_t smw;
        uint32_t bg = bpack2(v0, v1, smw);
        g_w2b[j] = bg; g_w2s[j] = smw;
    }
    for (int j = i0; j < 9*4*8*4; j += n) {
        int reg = j & 3, nq = (j >> 2) & 7, tt = (j >> 5) & 3;
        int s = (j >> 7) % 9;
        int co = nq + 8*(reg & 1);
        int pu = tt + 4*(reg >> 1);
        float v0 = 0.f, v1 = 0.f;
        if (co < 8) {
            v0 = w3[co*144 + pu*9 + s];
            v1 = w3[co*144 + (pu + 8)*9 + s];
        }
        uint32_t smw;
        uint32_t bg = bpack2(v0, v1, smw);
        g_w3b[j] = bg; g_w3s[j] = smw;
    }
}

// ---------------------------------------------------------------------------
// conv1: 4 -> 32, leaky. m16n8k8 tf32, K = 2 taps x 4 ci, 5 k-steps.
// Block 8 rows x 64 cols, 2 CTAs/SM.
// ---------------------------------------------------------------------------
__global__ __launch_bounds__(256, 2)
void conv1_k(const float* __restrict__ in, const float* __restrict__ bias) {
    __shared__ uint2 t1[4*684];
    const int tid = threadIdx.x;
    const int wid = tid >> 5, lane = tid & 31;
    const int nq = lane >> 2, tt = lane & 3;
    const int x0 = blockIdx.x * 64, y0 = blockIdx.y * 8, b = blockIdx.z;

    for (int i = tid; i < 4*10*66; i += 256) {
        int c = i / 660, rem = i % 660;
        int yy = rem / 66, xx = rem % 66;
        int gy = y0 + yy - 1, gx = x0 + xx - 1;
        float v = 0.f;
        if (gy >= 0 && gy < H && gx >= 0 && gx < W)
            v = in[(((size_t)b*4 + c)*H + gy)*W + gx];
        uint32_t vb, vs;
        tf_split(v, vb, vs);
        t1[c*684 + yy*68 + xx] = make_uint2(vb, vs);
    }
    __syncthreads();

    float acc[2][8][4];
#pragma unroll
    for (int m = 0; m < 2; m++)
#pragma unroll
        for (int g = 0; g < 8; g++)
#pragma unroll
            for (int q = 0; q < 4; q++) acc[m][g][q] = 0.f;

#pragma unroll
    for (int step = 0; step < 5; step++) {
        const int s0 = 2*step;
        const int s1 = (s0 + 1 <= 8) ? s0 + 1 : 8;   // pad tap: weights are zero
        const int kh0 = s0 / 3, kw0 = s0 % 3;
        const int kh1 = s1 / 3, kw1 = s1 % 3;

        // A fragments: a0=(nq, k=tt), a1=(nq+8, tt), a2=(nq, tt+4), a3=(nq+8, tt+4)
        int wb_lo = (step*8 + tt)*32;
        int wb_hi = (step*8 + tt + 4)*32;
        uint32_t ab0[4], as0[4], ab1[4], as1[4];
        ab0[0] = g_w1b[wb_lo + nq];      ab0[1] = g_w1b[wb_lo + nq + 8];
        ab0[2] = g_w1b[wb_hi + nq];      ab0[3] = g_w1b[wb_hi + nq + 8];
        as0[0] = g_w1s[wb_lo + nq];      as0[1] = g_w1s[wb_lo + nq + 8];
        as0[2] = g_w1s[wb_hi + nq];      as0[3] = g_w1s[wb_hi + nq + 8];
        ab1[0] = g_w1b[wb_lo + 16 + nq]; ab1[1] = g_w1b[wb_lo + 24 + nq];
        ab1[2] = g_w1b[wb_hi + 16 + nq]; ab1[3] = g_w1b[wb_hi + 24 + nq];
        as1[0] = g_w1s[wb_lo + 16 + nq]; as1[1] = g_w1s[wb_lo + 24 + nq];
        as1[2] = g_w1s[wb_hi + 16 + nq]; as1[3] = g_w1s[wb_hi + 24 + nq];

        int base0 = tt*684 + (wid + kh0)*68 + nq + kw0;
        int base1 = tt*684 + (wid + kh1)*68 + nq + kw1;
#pragma unroll
        for (int g = 0; g < 8; g++) {
            uint2 bv0 = t1[base0 + g*8];
            uint2 bv1 = t1[base1 + g*8];
            mma8(acc[0][g], ab0, bv0.x, bv1.x);
            mma8(acc[0][g], as0, bv0.x, bv1.x);
            mma8(acc[0][g], ab0, bv0.y, bv1.y);
            mma8(acc[1][g], ab1, bv0.x, bv1.x);
            mma8(acc[1][g], as1, bv0.x, bv1.x);
            mma8(acc[1][g], ab1, bv0.y, bv1.y);
        }
    }

    const int gy = y0 + wid;
#pragma unroll
    for (int m = 0; m < 2; m++) {
        int co0 = m*16 + nq;
        float b0 = bias[co0], b8 = bias[co0 + 8];
        size_t plane = (size_t)(b*16 + m*8 + nq);
#pragma unroll
        for (int g = 0; g < 8; g++) {
            int pe = x0 + g*8 + 2*tt;
            float v0 = lrelu(acc[m][g][0] + b0);
            float v1 = lrelu(acc[m][g][1] + b0);
            float v2 = lrelu(acc[m][g][2] + b8);
            float v3 = lrelu(acc[m][g][3] + b8);
            uint32_t se, so;
            uint32_t be = bpack2(v0, v2, se);
            uint32_t bo = bpack2(v1, v3, so);
            *(uint4*)&g_f1p[plane*PLANE + (size_t)gy*W + pe] = make_uint4(be, se, bo, so);
        }
    }
}

// ---------------------------------------------------------------------------
// conv2/conv3: bf16 m16n8k16, warp-per-row cp.async staging (rr invariant
// under pix+=32), incremental swizzled mainloop addressing.
// ---------------------------------------------------------------------------
template<int CHUNKS, int COUT, bool LEAKY, bool PACKOUT>
__global__ __launch_bounds__(256, 2)
void convP_k(const uint2* __restrict__ inp, const uint4* __restrict__ wb4,
             const uint4* __restrict__ ws4, const float* __restrict__ bias,
             uint2* __restrict__ outp, float* __restrict__ outf) {
    extern __shared__ uint2 tile[];   // [1188*8]
    const int tid = threadIdx.x;
    const int wid = tid >> 5, lane = tid & 31;
    const int nq = lane >> 2, tt = lane & 3;
    const int x0 = blockIdx.x * 64, y0 = blockIdx.y * 16, b = blockIdx.z;
    const uint32_t smem_base = (uint32_t)__cvta_generic_to_shared(tile);

    float acc[16][4];
#pragma unroll
    for (int g = 0; g < 16; g++)
#pragma unroll
        for (int q = 0; q < 4; q++) acc[g][q] = 0.f;

#pragma unroll 1
    for (int chunk = 0; chunk < CHUNKS; chunk++) {
        __syncthreads();
        {
            const uint2* gplane = inp + (((size_t)b*CHUNKS + chunk)*8)*PLANE;
#pragma unroll 1
            for (int yy = wid; yy < 18; yy += 8) {
                int gy = y0 + yy - 1;
                bool rowok = (gy >= 0) && (gy < H);
                int gyc = rowok ? gy : 0;
                int pix0 = yy*66 + lane;
                int rr = (pix0 + (pix0 >> 2)) & 3;
                bool ok0, ok1, ok2;
                {
                    int gx = x0 + lane - 1;
                    ok0 = rowok && (gx >= 0) && (gx < W);
                    ok1 = rowok && (lane < 34) && (gx + 32 < W);
                    ok2 = rowok && (lane < 2);
                }
                const uint2* grow = gplane + (size_t)gyc*W + (x0 - 1 + lane);
                uint32_t sbase = smem_base + (uint32_t)(pix0*8)*8u;
#pragma unroll
                for (int u = 0; u < 8; u++) {
                    int pos = 2*(((u & 3) + rr) & 3) + (u >> 2);
                    const uint2* gu = grow + (size_t)u*PLANE;
                    uint32_t su = sbase + (uint32_t)pos*8u;
                    cpasync8(su, ok0 ? gu : (const void*)inp, ok0);
                    if (lane < 34)
                        cpasync8(su + 2048u, ok1 ? (gu + 32) : (const void*)inp, ok1);
                    if (lane < 2)
                        cpasync8(su + 4096u, ok2 ? (gu + 64) : (const void*)inp, ok2);
                }
            }
        }
        asm volatile("cp.async.commit_group;\n");
        asm volatile("cp.async.wait_group 0;\n");
        __syncthreads();

#pragma unroll
        for (int s = 0; s < 9; s++) {
            const int kh = s / 3, kw = s % 3;
            uint4 A = wb4[((chunk*9 + s)*4 + tt)*8 + nq];
            uint4 S = ws4[((chunk*9 + s)*4 + tt)*8 + nq];
            uint32_t ab[4]  = {A.x, A.y, A.z, A.w};
            uint32_t as_[4] = {S.x, S.y, S.z, S.w};

            int pix0 = (2*wid + kh)*66 + nq + kw;
            int rr0 = (pix0 + (pix0 >> 2)) & 3;
            int t0 = pix0*8 + 2*((tt + rr0) & 3);
            int pix1 = pix0 + 66;
            int rr1 = (pix1 + (pix1 >> 2)) & 3;
            int t1 = pix1*8 + 2*((tt + rr1) & 3);
#pragma unroll
            for (int gg = 0; gg < 8; gg++) {
                uint4 Bv0 = *(const uint4*)&tile[t0];
                mma16(acc[gg], ab,  Bv0.x, Bv0.z);
                mma16(acc[gg], as_, Bv0.x, Bv0.z);
                mma16(acc[gg], ab,  Bv0.y, Bv0.w);
                uint4 Bv1 = *(const uint4*)&tile[t1];
                mma16(acc[8+gg], ab,  Bv1.x, Bv1.z);
                mma16(acc[8+gg], as_, Bv1.x, Bv1.z);
                mma16(acc[8+gg], ab,  Bv1.y, Bv1.w);
                t0 = (t0 + 64) ^ 4;
                t1 = (t1 + 64) ^ 4;
            }
        }
    }

    if (PACKOUT) {
        float b0 = bias[nq], b8 = bias[nq + 8];
        size_t plane = (size_t)(b*8 + nq);
#pragma unroll
        for (int g = 0; g < 16; g++) {
            int gy = y0 + 2*wid + (g >> 3);
            int pe = x0 + (g & 7)*8 + 2*tt;
            float v0 = acc[g][0] + b0, v1 = acc[g][1] + b0;
            float v2 = acc[g][2] + b8, v3 = acc[g][3] + b8;
            if (LEAKY) { v0 = lrelu(v0); v1 = lrelu(v1); v2 = lrelu(v2); v3 = lrelu(v3); }
            uint32_t se, so;
            uint32_t be = bpack2(v0, v2, se);
            uint32_t bo = bpack2(v1, v3, so);
            *(uint4*)&outp[plane*PLANE + (size_t)gy*W + pe] = make_uint4(be, se, bo, so);
        }
    } else {
        float b0 = bias[nq];
#pragma unroll
        for (int g = 0; g < 16; g++) {
            int gy = y0 + 2*wid + (g >> 3);
            int pe = x0 + (g & 7)*8 + 2*tt;
            float2 o0;
            o0.x = acc[g][0] + b0; o0.y = acc[g][1] + b0;
            if (LEAKY) { o0.x = lrelu(o0.x); o0.y = lrelu(o0.y); }
            *(float2*)&outf[(((size_t)b*COUT + nq)*H + gy)*W + pe] = o0;
        }
    }
}

// ---------------------------------------------------------------------------
// Multi-scale box std maps — prefetch hoisted above the scan
// ---------------------------------------------------------------------------
__device__ __forceinline__ int refl(int i) {
    return i < 0 ? -i : (i > H - 1 ? 2*(H - 1) - i : i);
}

__global__ __launch_bounds__(512)
void boxstd_k() {
    constexpr int ROWS = 64;
    extern __shared__ float bsm[];
    float* csA  = bsm;
    float* csB  = bsm + 4096;
    float* pref = bsm + 8192;

    const int j    = threadIdx.x;
    const int lane = j & 31;
    const int wid  = j >> 5;
    const int strip = blockIdx.x;
    const int scale = blockIdx.y;
    const int b     = blockIdx.z;

    const int K = (scale == 0) ? 11 : (scale == 1) ? 25 : 49;
    const int P = K >> 1;
    const float inv = 1.f / (float)(K * K);
    const int r0 = strip * ROWS;

    for (int c = 0; c < 8; c++) {
        const float* fp = g_f + ((size_t)(b*8 + c)) * PLANE;
        float s = 0.f, s2 = 0.f;
        for (int i = r0 - P; i <= r0 + P; i++) {
            float v = fp[refl(i)*W + j];
            s += v;
            s2 = fmaf(v, v, s2);
        }
        csA[c*512 + j] = s;
        csB[c*512 + j] = s2;
    }

    const int sc = wid & 7, sq = wid >> 3;
    float* src = (sq ? csB : csA) + sc*512;
    float* pr  = pref + wid*513;

    for (int r = r0; r < r0 + ROWS; r++) {
        __syncthreads();

        float nva[8], nvs[8];
        const bool more = (r + 1 < r0 + ROWS);
        if (more) {
            int ra = refl(r + 1 + P), rs = refl(r - P);
#pragma unroll
            for (int c = 0; c < 8; c++) {
                const float* fp = g_f + ((size_t)(b*8 + c)) * PLANE;
                nva[c] = fp[ra*W + j];
                nvs[c] = fp[rs*W + j];
            }
        }

        {
            float seg[16];
            float run = 0.f;
            int base = lane * 16;
#pragma unroll
            for (int i = 0; i < 16; i++) { run += src[base + i]; seg[i] = run; }
            float v = run;
#pragma unroll
            for (int d = 1; d < 32; d <<= 1) {
                float t = __shfl_up_sync(0xffffffffu, v, d);
                if (lane >= d) v += t;
            }
            float carry = v - run;
#pragma unroll
            for (int i = 0; i < 16; i++) pr[base + 1 + i] = seg[i] + carry;
            if (lane == 0) pr[0] = 0.f;
        }
        __syncthreads();

        const int lo = j - P, hi = j + P;
        const int loC = max(lo, 0), hiC = min(hi, W - 1);
        float rowacc = 0.f;
#pragma unroll
        for (int c = 0; c < 8; c++) {
            const float* pA = pref + c*513;
            const float* pB = pref + (8 + c)*513;
            float Sx = pA[hiC + 1] - pA[loC];
            float Sy = pB[hiC + 1] - pB[loC];
            if (lo < 0) {
                Sx += pA[-lo + 1] - pA[1];
                Sy += pB[-lo + 1] - pB[1];
            }
            if (hi > W - 1) {
                Sx += pA[W - 1] - pA[2*(W - 1) - hi];
                Sy += pB[W - 1] - pB[2*(W - 1) - hi];
            }
            float m  = Sx * inv;
            float m2 = Sy * inv;
            rowacc += sqrtf(fmaxf(m2 - m*m, 1e-6f));
        }
        g_maps[(size_t)scale*NPIX + ((size_t)b*H + r)*W + j] =
            powf(rowacc * 0.125f, 0.8f);

        if (more) {
#pragma unroll
            for (int c = 0; c < 8; c++) {
                csA[c*512 + j] += nva[c] - nvs[c];
                csB[c*512 + j] += nva[c]*nva[c] - nvs[c]*nvs[c];
            }
        }
    }
}

// ---------------------------------------------------------------------------
// Fusion + level-1 histogram
// ---------------------------------------------------------------------------
__global__ void fuse_hist1_k(const float* __restrict__ fw, const float* __restrict__ fb) {
    __shared__ unsigned h[8192];
    for (int i = threadIdx.x; i < 8192; i += blockDim.x) h[i] = 0u;
    __syncthreads();
    const float w0 = fw[0], w1 = fw[1], w2 = fw[2], b0 = fb[0];
    const size_t N = NPIX;
    for (size_t i = (size_t)blockIdx.x*blockDim.x + threadIdx.x; i < N;
         i += (size_t)gridDim.x*blockDim.x) {
        float v = w0*g_maps[i] + w1*g_maps[i + N] + w2*g_maps[i + 2*N] + b0;
        v = fmaxf(v, 0.f);
        g_fused[i] = v;
        atomicAdd(&h[__float_as_uint(v) >> 19], 1u);
    }
    __syncthreads();
    for (int i = threadIdx.x; i < 8192; i += blockDim.x)
        if (h[i]) atomicAdd(&g_h1[i], h[i]);
}

__device__ void findRank(const unsigned* __restrict__ hist, int nbins, unsigned rank,
                         unsigned* sbin, unsigned* srem,
                         unsigned* sp, unsigned* sb) {
    __syncthreads();
    const int tid = threadIdx.x;
    const int chunk = nbins / 256;
    unsigned loc = 0;
    for (int i = 0; i < chunk; i++) loc += hist[tid*chunk + i];
    sp[tid] = loc;
    __syncthreads();
    if (tid == 0) {
        unsigned c = 0;
        for (int i = 0; i < 256; i++) { sb[i] = c; c += sp[i]; }
    }
    __syncthreads();
    unsigned cum = sb[tid];
    for (int i = 0; i < chunk; i++) {
        unsigned cnt = hist[tid*chunk + i];
        if (rank >= cum && rank < cum + cnt) { *sbin = tid*chunk + i; *srem = rank - cum; }
        cum += cnt;
    }
    __syncthreads();
}

__global__ void scan1_k() {
    __shared__ unsigned sp[256], sb[256];
    __shared__ unsigned rbin, rrem;
    const unsigned ranks[4] = {524287u, 524288u, 1572863u, 1572864u};
    for (int r = 0; r < 4; r++) {
        findRank(g_h1, 8192, ranks[r], &rbin, &rrem, sp, sb);
        if (threadIdx.x == 0) { g_qs.pref1[r] = rbin; g_qs.rem[r] = rrem; }
        __syncthreads();
    }
}

__global__ void hist2_k() {
    extern __shared__ unsigned h2s[];   // 4*8192
    for (int i = threadIdx.x; i < 4*8192; i += blockDim.x) h2s[i] = 0u;
    __syncthreads();
    unsigned p0 = g_qs.pref1[0], p1 = g_qs.pref1[1];
    unsigned p2 = g_qs.pref1[2], p3 = g_qs.pref1[3];
    const uint4* fp = (const uint4*)g_fused;
    const size_t N4 = NPIX/4;
    for (size_t i = (size_t)blockIdx.x*blockDim.x + threadIdx.x; i < N4;
         i += (size_t)gridDim.x*blockDim.x) {
        uint4 v = fp[i];
        uint32_t bb[4] = {v.x, v.y, v.z, v.w};
#pragma unroll
        for (int e = 0; e < 4; e++) {
            unsigned hi = bb[e] >> 19, mid = (bb[e] >> 6) & 8191u;
            if (hi == p0) atomicAdd(&h2s[mid], 1u);
            if (hi == p1) atomicAdd(&h2s[8192 + mid], 1u);
            if (hi == p2) atomicAdd(&h2s[16384 + mid], 1u);
            if (hi == p3) atomicAdd(&h2s[24576 + mid], 1u);
        }
    }
    __syncthreads();
    for (int i = threadIdx.x; i < 4*8192; i += blockDim.x)
        if (h2s[i]) atomicAdd(&g_h2[i], h2s[i]);
}

__global__ void scan2_k() {
    __shared__ unsigned sp[256], sb[256];
    __shared__ unsigned rbin, rrem;
    for (int r = 0; r < 4; r++) {
        unsigned rank = g_qs.rem[r];
        findRank(g_h2 + r*8192, 8192, rank, &rbin, &rrem, sp, sb);
        if (threadIdx.x == 0) {
            g_qs.pref2[r] = (g_qs.pref1[r] << 13) | rbin;
            g_qs.rem[r]   = rrem;
        }
        __syncthreads();
    }
}

__global__ void hist3_k() {
    __shared__ unsigned h[4*64];
    for (int i = threadIdx.x; i < 4*64; i += blockDim.x) h[i] = 0u;
    __syncthreads();
    unsigned p0 = g_qs.pref2[0], p1 = g_qs.pref2[1];
    unsigned p2 = g_qs.pref2[2], p3 = g_qs.pref2[3];
    const uint4* fp = (const uint4*)g_fused;
    const size_t N4 = NPIX/4;
    for (size_t i = (size_t)blockIdx.x*blockDim.x + threadIdx.x; i < N4;
         i += (size_t)gridDim.x*blockDim.x) {
        uint4 v = fp[i];
        uint32_t bb[4] = {v.x, v.y, v.z, v.w};
#pragma unroll
        for (int e = 0; e < 4; e++) {
            unsigned hi = bb[e] >> 6, lo = bb[e] & 63u;
            if (hi == p0) atomicAdd(&h[lo], 1u);
            if (hi == p1) atomicAdd(&h[64 + lo], 1u);
            if (hi == p2) atomicAdd(&h[128 + lo], 1u);
            if (hi == p3) atomicAdd(&h[192 + lo], 1u);
        }
    }
    __syncthreads();
    for (int i = threadIdx.x; i < 4*64; i += blockDim.x)
        if (h[i]) atomicAdd(&g_h3[i], h[i]);
}

__global__ void xstats_k(const float* __restrict__ x) {
    const int bc = blockIdx.x;
    const int sl = blockIdx.y;
    const float* p = x + ((size_t)bc << 18) + (size_t)sl * 32768;
    float s = 0.f, s2 = 0.f;
    for (int i = threadIdx.x; i < 32768; i += 256) {
        float v = p[i];
        s += v;
        s2 = fmaf(v, v, s2);
    }
#pragma unroll
    for (int o = 16; o; o >>= 1) {
        s  += __shfl_xor_sync(0xffffffffu, s, o);
        s2 += __shfl_xor_sync(0xffffffffu, s2, o);
    }
    __shared__ float ss[8], ss2[8];
    int w = threadIdx.x >> 5, l = threadIdx.x & 31;
    if (l == 0) { ss[w] = s; ss2[w] = s2; }
    __syncthreads();
    if (threadIdx.x == 0) {
        float a = 0.f, a2 = 0.f;
        for (int i = 0; i < 8; i++) { a += ss[i]; a2 += ss2[i]; }
        atomicAdd(&g_stats[bc].x, a);
        atomicAdd(&g_stats[bc].y, a2);
    }
}

// scan3 + thresholds fused (1 warp)
__global__ void scan3thr_k(const float* __restrict__ chw) {
    __shared__ float sv[4];
    const int t = threadIdx.x;
    if (t < 4) {
        unsigned rank = g_qs.rem[t];
        unsigned cum = 0, bin = 0;
        for (int i = 0; i < 64; i++) {
            unsigned c = g_h3[t*64 + i];
            if (rank >= cum && rank < cum + c) bin = (unsigned)i;
            cum += c;
        }
        sv[t] = __uint_as_float((g_qs.pref2[t] << 6) | bin);
    }
    __syncthreads();
    float q25 = sv[0] + 0.75f*(sv[1] - sv[0]);
    float q75 = sv[2] + 0.25f*(sv[3] - sv[2]);
    float iqr = q75 - q25;
    if (iqr < 1e-5f) iqr = 0.05f;

    const int c = t & 3;
    float w0 = chw[0], w1 = chw[1], w2 = chw[2], w3 = chw[3];
    float mx = fmaxf(fmaxf(w0, w1), fmaxf(w2, w3));
    float e0 = expf(w0 - mx), e1 = expf(w1 - mx), e2 = expf(w2 - mx), e3 = expf(w3 - mx);
    float se = e0 + e1 + e2 + e3;
    float cw = ((c == 0) ? e0 : (c == 1) ? e1 : (c == 2) ? e2 : e3) / se;

    float2 st = g_stats[t];
    const float N = (float)PLANE;
    float var = (st.y - st.x*st.x/N) / (N - 1.f);
    float gstd = sqrtf(fmaxf(var, 0.f));

    float lower = q25 - 0.5f*iqr;
    float upper = q75 + 0.5f*iqr;
    float gf = fminf(fmaxf(gstd*5.f, 0.5f), 2.f);
    lower *= gf; upper *= gf;
    float cf = fminf(fmaxf(cw*gstd*2.f, 0.8f), 1.2f);
    lower *= cf; upper *= cf;

    float d = fabsf(upper - lower);
#pragma unroll
    for (int o = 16; o; o >>= 1) d = fminf(d, __shfl_xor_sync(0xffffffffu, d, o));
    if (d < 1e-5f) {
        float mt = 0.5f*(upper + lower);
        lower = mt - 0.05f;
        upper = mt + 0.05f;
    }
    g_thr[t]      = lower;
    g_thr[32 + t] = fmaxf(upper - lower, 1e-5f);
}

__global__ void mask_k(float* __restrict__ out) {
    for (size_t i = (size_t)blockIdx.x*blockDim.x + threadIdx.x; i < (size_t)NPIX;
         i += (size_t)gridDim.x*blockDim.x) {
        int b = (int)(i >> 18);
        float v = g_fused[i];
        float acc = 0.f;
#pragma unroll
        for (int c = 0; c < 4; c++) {
            float lo  = g_thr[b*4 + c];
            float dif = g_thr[32 + b*4 + c];
            float nrm = fminf(fmaxf((v - lo)/dif, 0.f), 1.f);
            acc += 1.f/(1.f + expf(3.f - 6.f*nrm));
        }
        out[i] = 0.25f*acc;
    }
}

// ---------------------------------------------------------------------------
// Launch
// ---------------------------------------------------------------------------
extern "C" void kernel_launch(void* const* d_in, const int* in_sizes, int n_in,
                              void* d_out, int out_size) {
    const float* x        = (const float*)d_in[0];
    const float* conv1_w  = (const float*)d_in[1];
    const float* conv1_b  = (const float*)d_in[2];
    const float* conv2_w  = (const float*)d_in[3];
    const float* conv2_b  = (const float*)d_in[4];
    const float* conv3_w  = (const float*)d_in[5];
    const float* conv3_b  = (const float*)d_in[6];
    const float* fusion_w = (const float*)d_in[7];
    const float* fusion_b = (const float*)d_in[8];
    const float* chw      = (const float*)d_in[9];
    float* out = (float*)d_out;

    uint2* f1p; cudaGetSymbolAddress((void**)&f1p, g_f1p);
    uint2* f2p; cudaGetSymbolAddress((void**)&f2p, g_f2p);
    float* f  ; cudaGetSymbolAddress((void**)&f  , g_f);
    uint4 *w2b, *w2s, *w3b, *w3s;
    cudaGetSymbolAddress((void**)&w2b, g_w2b);
    cudaGetSymbolAddress((void**)&w2s, g_w2s);
    cudaGetSymbolAddress((void**)&w3b, g_w3b);
    cudaGetSymbolAddress((void**)&w3s, g_w3s);

    const int smemP  = 1188 * 8 * 8;                 // 76032
    const int smemBX = (4096 + 4096 + 16*513) * 4;   // 65668
    const int smemH2 = 4 * 8192 * 4;                 // 131072
    cudaFuncSetAttribute(convP_k<2, 16, true, true>,  cudaFuncAttributeMaxDynamicSharedMemorySize, smemP);
    cudaFuncSetAttribute(convP_k<1, 8, false, false>, cudaFuncAttributeMaxDynamicSharedMemorySize, smemP);
    cudaFuncSetAttribute(boxstd_k, cudaFuncAttributeMaxDynamicSharedMemorySize, smemBX);
    cudaFuncSetAttribute(hist2_k,  cudaFuncAttributeMaxDynamicSharedMemorySize, smemH2);

    prep_k<<<32, 256>>>(conv1_w, conv2_w, conv3_w);
    xstats_k<<<dim3(32, 8), 256>>>(x);

    conv1_k<<<dim3(W/64, H/8, B), 256>>>(x, conv1_b);
    convP_k<2, 16, true, true><<<dim3(W/64, H/16, B), 256, smemP>>>(f1p, w2b, w2s, conv2_b, f2p, 0);
    convP_k<1, 8, false, false><<<dim3(W/64, H/16, B), 256, smemP>>>(f2p, w3b, w3s, conv3_b, 0, f);

    boxstd_k<<<dim3(H/64, 3, B), 512, smemBX>>>();

    fuse_hist1_k<<<448, 256>>>(fusion_w, fusion_b);
    scan1_k<<<1, 256>>>();
    hist2_k<<<148, 512, smemH2>>>();
    scan2_k<<<1, 256>>>();
    hist3_k<<<256, 256>>>();
    scan3thr_k<<<1, 32>>>(chw);

    mask_k<<<1024, 256>>>(out);
}